// round 15
// baseline (speedup 1.0000x reference)
#include <cuda_runtime.h>
#include <cuda_bf16.h>
#include <cuda_fp16.h>
#include <math.h>
#include <stdint.h>

#define T_SEQ 2048
#define HID   4096
#define NH    32
#define NKV   8
#define GQ    4
#define DH    128
#define WIN   64
#define QKV_W 6144
#define SCALE 0.08838834764831845f

// ---------------- scratch ---------------------------------------------------
__device__ float g_qkv[(size_t)T_SEQ * QKV_W];
__device__ float g_og[(size_t)T_SEQ * HID];     // global attn out (fp32)
__device__ float g_gate[T_SEQ * NH];
__device__ float g_cosT[T_SEQ * 64];
__device__ float g_sinT[T_SEQ * 64];

// fp16 GEMM operands (symmetric single-fp16)
__device__ __half g_hid16[(size_t)T_SEQ * HID];
__device__ __half g_wqkv16[(size_t)QKV_W * HID];
__device__ __half g_wo16[(size_t)HID * HID];
__device__ __half g_og16[(size_t)T_SEQ * HID];   // gated combined out

// attention operands: Q fp16 hi/lo (scaled), K/V single fp16
__device__ __half g_q_hi[(size_t)T_SEQ * NH * DH];
__device__ __half g_q_lo[(size_t)T_SEQ * NH * DH];
__device__ __half g_k16[(size_t)T_SEQ * NKV * DH];
__device__ __half g_v16[(size_t)T_SEQ * NKV * DH];
// local-window k/v (post-rope, from qkv projection), single fp16
__device__ __half g_kl16[(size_t)T_SEQ * NKV * DH];
__device__ __half g_vl16[(size_t)T_SEQ * NKV * DH];

// ================= low-level helpers =========================================
__device__ __forceinline__ uint32_t smem_u32(const void* p) {
    uint32_t a;
    asm("{ .reg .u64 t; cvta.to.shared.u64 t, %1; cvt.u32.u64 %0, t; }"
        : "=r"(a) : "l"(p));
    return a;
}
__device__ __forceinline__ void cpa16(uint32_t dst, const void* src) {
    asm volatile("cp.async.cg.shared.global [%0], [%1], 16;"
                 :: "r"(dst), "l"(src) : "memory");
}
#define CP_COMMIT() asm volatile("cp.async.commit_group;" ::: "memory")
#define CP_WAIT(n)  asm volatile("cp.async.wait_group %0;" :: "n"(n) : "memory")

__device__ __forceinline__ void ldsm4(uint32_t* r, uint32_t addr) {
    asm volatile("ldmatrix.sync.aligned.m8n8.x4.shared.b16 {%0,%1,%2,%3}, [%4];"
                 : "=r"(r[0]), "=r"(r[1]), "=r"(r[2]), "=r"(r[3]) : "r"(addr));
}
__device__ __forceinline__ void ldsm4t(uint32_t* r, uint32_t addr) {
    asm volatile("ldmatrix.sync.aligned.m8n8.x4.trans.shared.b16 {%0,%1,%2,%3}, [%4];"
                 : "=r"(r[0]), "=r"(r[1]), "=r"(r[2]), "=r"(r[3]) : "r"(addr));
}
__device__ __forceinline__ void mma16816h(float* d, const uint32_t* a,
                                          const uint32_t* b) {
    asm volatile(
        "mma.sync.aligned.m16n8k16.row.col.f32.f16.f16.f32 "
        "{%0,%1,%2,%3}, {%4,%5,%6,%7}, {%8,%9}, {%0,%1,%2,%3};"
        : "+f"(d[0]), "+f"(d[1]), "+f"(d[2]), "+f"(d[3])
        : "r"(a[0]), "r"(a[1]), "r"(a[2]), "r"(a[3]), "r"(b[0]), "r"(b[1]));
}
__device__ __forceinline__ uint32_t pack_f16x2(float x, float y) {
    __half2 h = __floats2half2_rn(x, y);
    return *(uint32_t*)&h;
}
__device__ __forceinline__ void pack_hilo_f16(float x, float y,
                                              uint32_t& hi, uint32_t& lo) {
    __half hx = __float2half_rn(x), hy = __float2half_rn(y);
    float rx = x - __half2float(hx), ry = y - __half2float(hy);
    __half lx = __float2half_rn(rx), ly = __float2half_rn(ry);
    hi = (uint32_t)__half_as_ushort(hx) | ((uint32_t)__half_as_ushort(hy) << 16);
    lo = (uint32_t)__half_as_ushort(lx) | ((uint32_t)__half_as_ushort(ly) << 16);
}

// ---------------- trig table -------------------------------------------------
__global__ void build_trig_kernel(const int* __restrict__ positions) {
    int i = blockIdx.x * blockDim.x + threadIdx.x;
    if (i >= T_SEQ * 64) return;
    int t = i >> 6, d = i & 63;
    double inv = pow(10000.0, -(double)d / 64.0);
    double ang = (double)positions[t] * inv;
    g_cosT[i] = (float)cos(ang);
    g_sinT[i] = (float)sin(ang);
}

// ---------------- fp32 -> fp16 single ------------------------------------------
__global__ void __launch_bounds__(256) cvt_f16(
    const float* __restrict__ x, __half* __restrict__ y, int n4)
{
    int i = blockIdx.x * blockDim.x + threadIdx.x;
    if (i >= n4) return;
    float4 v = ((const float4*)x)[i];
    uint2 o;
    o.x = pack_f16x2(v.x, v.y);
    o.y = pack_f16x2(v.z, v.w);
    ((uint2*)y)[i] = o;
}

// ====== symmetric fp16 MMA GEMM: C[M,N] = A16[M,K] * B16[N,K]^T ===============
// 256x128 CTA tile, 512 threads, 16 warps (4M x 4N), 64x32 warp tiles.
// L2 traffic per output = (1/256 + 1/128) vs (1/128 + 1/128): x0.75.
#define STAGES 2
#define STG_B  24576                 // A 16KB + B 8KB
#define GEMM_SMEM (STAGES * STG_B)

__device__ __forceinline__ void load_stage(
    uint32_t sbase, int stage, int c,
    const __half* __restrict__ A, const __half* __restrict__ B,
    int bm, int bn, int K, int tid)
{
    const int k0 = c * 32;
    const uint32_t st = sbase + stage * STG_B;
#pragma unroll
    for (int j = 0; j < 3; ++j) {
        int l = tid + j * 512;            // 0..1535
        const bool isB = (j == 2);        // compile-time per j
        int li = isB ? (l - 1024) : l;    // A: 0..1023, B: 0..511
        int row = li >> 2;
        int ch = li & 3;
        uint32_t dst = st + (isB ? 16384u : 0u) + (uint32_t)row * 64u
                     + (uint32_t)((ch ^ ((row >> 1) & 3)) << 4);
        const __half* src = isB
            ? B + (size_t)(bn + row) * K + k0 + ch * 8
            : A + (size_t)(bm + row) * K + k0 + ch * 8;
        cpa16(dst, src);
    }
}

__global__ void __launch_bounds__(512, 2) gemm_f16(
    const __half* __restrict__ A, const __half* __restrict__ B,
    float* __restrict__ C, int M, int N, int K)
{
    extern __shared__ char smem[];
    const uint32_t sbase = smem_u32(smem);
    const int tid = threadIdx.x;
    const int wid = tid >> 5, lane = tid & 31;
    const int bm = blockIdx.y * 256, bn = blockIdx.x * 128;
    const int wm = (wid & 3) * 64;      // warp M band (64 rows)
    const int wn = (wid >> 2) * 32;     // warp N band (32 cols)

    float acc[4][4][4];
#pragma unroll
    for (int mi = 0; mi < 4; ++mi)
#pragma unroll
        for (int ni = 0; ni < 4; ++ni)
#pragma unroll
            for (int k = 0; k < 4; ++k) acc[mi][ni][k] = 0.f;

    const int nch = K / 32;

    load_stage(sbase, 0, 0, A, B, bm, bn, K, tid);
    CP_COMMIT();

    uint32_t offA[4], offB[2];
    int swA[4], swB[2];
#pragma unroll
    for (int mi = 0; mi < 4; ++mi) {
        int row = wm + mi * 16 + (lane & 15);
        offA[mi] = (uint32_t)row * 64u;
        swA[mi] = (row >> 1) & 3;
    }
#pragma unroll
    for (int nj = 0; nj < 2; ++nj) {
        int row = wn + nj * 16 + ((lane >> 4) << 3) + (lane & 7);
        offB[nj] = (uint32_t)row * 64u;
        swB[nj] = (row >> 1) & 3;
    }
    const int chA = (lane >> 4);
    const int chB = ((lane >> 3) & 1);

    for (int c = 0; c < nch; ++c) {
        CP_WAIT(0);
        __syncthreads();
        if (c + 1 < nch)
            load_stage(sbase, (c + 1) & 1, c + 1, A, B, bm, bn, K, tid);
        CP_COMMIT();

        const uint32_t st = sbase + (uint32_t)(c & 1) * STG_B;
#pragma unroll
        for (int ks = 0; ks < 2; ++ks) {
            uint32_t ra[4][4], rb[2][4];
#pragma unroll
            for (int mi = 0; mi < 4; ++mi) {
                int ch = ks * 2 + chA;
                uint32_t o = offA[mi] + (uint32_t)((ch ^ swA[mi]) << 4);
                ldsm4(ra[mi], st + o);
            }
#pragma unroll
            for (int nj = 0; nj < 2; ++nj) {
                int ch = ks * 2 + chB;
                uint32_t o = offB[nj] + (uint32_t)((ch ^ swB[nj]) << 4);
                ldsm4(rb[nj], st + 16384u + o);
            }
#pragma unroll
            for (int mi = 0; mi < 4; ++mi)
#pragma unroll
                for (int ni = 0; ni < 4; ++ni) {
                    const uint32_t* b2 = &rb[ni >> 1][(ni & 1) * 2];
                    mma16816h(acc[mi][ni], ra[mi], b2);
                }
        }
        __syncthreads();
    }

    const int g = lane >> 2, q = lane & 3;
#pragma unroll
    for (int mi = 0; mi < 4; ++mi)
#pragma unroll
        for (int ni = 0; ni < 4; ++ni) {
            int r0 = bm + wm + mi * 16 + g;
            int col = bn + wn + ni * 8 + q * 2;
            float2 v0 = make_float2(acc[mi][ni][0], acc[mi][ni][1]);
            float2 v1 = make_float2(acc[mi][ni][2], acc[mi][ni][3]);
            *(float2*)(C + (size_t)r0 * N + col) = v0;
            *(float2*)(C + (size_t)(r0 + 8) * N + col) = v1;
        }
}

// ---------------- RoPE + gate + fp16 exports ------------------------------------
__global__ void __launch_bounds__(256) rope_gate_kernel(
    const float* __restrict__ w_gate, const float* __restrict__ b_gate)
{
    int t = blockIdx.x;
    float* row = g_qkv + (size_t)t * QKV_W;

    for (int idx = threadIdx.x; idx < 48 * 64; idx += 256) {
        int head = idx >> 6;
        int d = idx & 63;
        if (head < NH) {                       // q heads: rope + scaled fp16 hi/lo
            int base = head * DH;
            float c = g_cosT[t * 64 + d];
            float s = g_sinT[t * 64 + d];
            float x1 = row[base + d];
            float x2 = row[base + d + 64];
            float y1 = x1 * c - x2 * s;
            float y2 = x2 * c + x1 * s;
            row[base + d]      = y1;           // for gate
            row[base + d + 64] = y2;
            size_t qi = ((size_t)t * NH + head) * DH + d;
            float a1 = y1 * SCALE, a2 = y2 * SCALE;
            __half h1 = __float2half_rn(a1);
            __half h2 = __float2half_rn(a2);
            g_q_hi[qi]      = h1;
            g_q_hi[qi + 64] = h2;
            g_q_lo[qi]      = __float2half_rn(a1 - __half2float(h1));
            g_q_lo[qi + 64] = __float2half_rn(a2 - __half2float(h2));
        } else if (head < NH + NKV) {          // k heads: rope + single fp16
            int gk = head - NH;
            int base = HID + gk * DH;
            float c = g_cosT[t * 64 + d];
            float s = g_sinT[t * 64 + d];
            float x1 = row[base + d];
            float x2 = row[base + d + 64];
            float y1 = x1 * c - x2 * s;
            float y2 = x2 * c + x1 * s;
            size_t ki = ((size_t)t * NKV + gk) * DH + d;
            g_kl16[ki]      = __float2half_rn(y1);
            g_kl16[ki + 64] = __float2half_rn(y2);
        } else {                               // v heads: single fp16
            int gv = head - NH - NKV;
            int base = HID + NKV * DH + gv * DH;
            size_t vi = ((size_t)t * NKV + gv) * DH + d;
            g_vl16[vi]      = __float2half_rn(row[base + d]);
            g_vl16[vi + 64] = __float2half_rn(row[base + d + 64]);
        }
    }
    __syncthreads();

    int wid = threadIdx.x >> 5, lane = threadIdx.x & 31;
    for (int h = wid; h < NH; h += 8) {
        const float* q = row + h * DH;
        const float* w = w_gate + h * DH;
        float acc = q[lane] * w[lane] + q[lane + 32] * w[lane + 32]
                  + q[lane + 64] * w[lane + 64] + q[lane + 96] * w[lane + 96];
#pragma unroll
        for (int off = 16; off; off >>= 1)
            acc += __shfl_xor_sync(0xffffffffu, acc, off);
        if (lane == 0)
            g_gate[t * NH + h] = 1.f / (1.f + __expf(-(acc + b_gate[h])));
    }
}

// ================= MMA flash attention (global causal, GQA-shared KV) =========
#define ATTN_SMEM 131072   // Q 64KB + 2 x (K 16KB + V 16KB)

__device__ __forceinline__ void attn_load_kv(
    uint32_t buf, int s0, int g, int tid,
    const __half* k16, const __half* v16)
{
#pragma unroll
    for (int j = 0; j < 4; ++j) {
        int slot = tid + j * 256;
        int row = slot >> 4;
        int ch = slot & 15;
        uint32_t off = (uint32_t)row * 256u + (uint32_t)((ch ^ (row & 7)) << 4);
        size_t gi = ((size_t)(s0 + row) * NKV + g) * DH + ch * 8;
        cpa16(buf + off, k16 + gi);
        cpa16(buf + 16384u + off, v16 + gi);
    }
}

__global__ void __launch_bounds__(256, 1) attn_mma(
    const __half* __restrict__ qh_g, const __half* __restrict__ ql_g,
    const __half* __restrict__ k_g, const __half* __restrict__ v_g)
{
    extern __shared__ char smem[];
    const uint32_t sb = smem_u32(smem);
    const int tid = threadIdx.x, wid = tid >> 5, lane = tid & 31;
    const int g = blockIdx.y;
    const int T0 = (gridDim.x - 1 - blockIdx.x) * 32;   // heavy blocks first
    const int nblk = (T0 + 32 + 63) / 64;

    const uint32_t QH = sb, QL = sb + 32768u;
    const uint32_t KV0 = sb + 65536u;

#pragma unroll
    for (int j = 0; j < 8; ++j) {
        int slot = tid + j * 256;
        int row = slot >> 4;               // 0..127
        int ch = slot & 15;
        uint32_t off = (uint32_t)row * 256u + (uint32_t)((ch ^ (row & 7)) << 4);
        int tt = row & 31;
        int hi = row >> 5;
        size_t gi = ((size_t)(T0 + tt) * NH + (g * GQ + hi)) * DH + ch * 8;
        cpa16(QH + off, qh_g + gi);
        cpa16(QL + off, ql_g + gi);
    }
    attn_load_kv(KV0, 0, g, tid, k_g, v_g);
    CP_COMMIT();

    const int mrow = wid * 16;
    const int rq = mrow + (lane & 15);
    const uint32_t qbase = (uint32_t)rq * 256u;
    const int cq = lane >> 4;
    const int rk = (lane & 7) | ((lane & 16) >> 1);
    const int ck = (lane >> 3) & 1;
    const int rv = lane & 15;
    const int cv = lane >> 4;
    const int wh = mrow >> 5;
    const int wtt = mrow & 31;

    float o[16][4];
#pragma unroll
    for (int i = 0; i < 16; ++i)
#pragma unroll
        for (int j = 0; j < 4; ++j) o[i][j] = 0.f;
    float m0 = -1e30f, m1 = -1e30f, l0 = 0.f, l1 = 0.f;

    for (int blk = 0; blk < nblk; ++blk) {
        if (blk + 1 < nblk)
            attn_load_kv(KV0 + (uint32_t)((blk + 1) & 1) * 32768u,
                         (blk + 1) * 64, g, tid, k_g, v_g);
        CP_COMMIT();
        CP_WAIT(1);
        __syncthreads();

        const int s0 = blk * 64;
        const bool active = (s0 <= T0 + wtt + 15);
        if (active) {
            const uint32_t buf = KV0 + (uint32_t)(blk & 1) * 32768u;
            const uint32_t Kb = buf, Vb = buf + 16384u;

            float s[8][4];
#pragma unroll
            for (int i = 0; i < 8; ++i)
#pragma unroll
                for (int j = 0; j < 4; ++j) s[i][j] = 0.f;

#pragma unroll
            for (int k = 0; k < 8; ++k) {
                uint32_t qa = qbase + (uint32_t)((((2 * k + cq) ^ (rq & 7))) << 4);
                uint32_t aqh[4], aql[4];
                ldsm4(aqh, QH + qa);
                ldsm4(aql, QL + qa);
#pragma unroll
                for (int nt2 = 0; nt2 < 4; ++nt2) {
                    uint32_t ka = (uint32_t)(nt2 * 16 + rk) * 256u
                                + (uint32_t)(((2 * k + ck) ^ (rk & 7)) << 4);
                    uint32_t bk[4];
                    ldsm4(bk, Kb + ka);
                    mma16816h(s[2 * nt2], aqh, bk);
                    mma16816h(s[2 * nt2], aql, bk);
                    mma16816h(s[2 * nt2 + 1], aqh, bk + 2);
                    mma16816h(s[2 * nt2 + 1], aql, bk + 2);
                }
            }

            if (s0 + 63 > T0 + wtt) {
                const int tr0 = T0 + wtt + (lane >> 2);
                const int tr1 = tr0 + 8;
#pragma unroll
                for (int nt = 0; nt < 8; ++nt) {
                    int sc = s0 + nt * 8 + 2 * (lane & 3);
                    if (sc > tr0)     s[nt][0] = -1e9f;
                    if (sc + 1 > tr0) s[nt][1] = -1e9f;
                    if (sc > tr1)     s[nt][2] = -1e9f;
                    if (sc + 1 > tr1) s[nt][3] = -1e9f;
                }
            }

            float mx0 = -1e30f, mx1 = -1e30f;
#pragma unroll
            for (int nt = 0; nt < 8; ++nt) {
                mx0 = fmaxf(mx0, fmaxf(s[nt][0], s[nt][1]));
                mx1 = fmaxf(mx1, fmaxf(s[nt][2], s[nt][3]));
            }
            mx0 = fmaxf(mx0, __shfl_xor_sync(0xffffffffu, mx0, 1));
            mx0 = fmaxf(mx0, __shfl_xor_sync(0xffffffffu, mx0, 2));
            mx1 = fmaxf(mx1, __shfl_xor_sync(0xffffffffu, mx1, 1));
            mx1 = fmaxf(mx1, __shfl_xor_sync(0xffffffffu, mx1, 2));
            float nm0 = fmaxf(m0, mx0), nm1 = fmaxf(m1, mx1);
            float cor0 = __expf(m0 - nm0), cor1 = __expf(m1 - nm1);
            m0 = nm0; m1 = nm1;

            float sum0 = 0.f, sum1 = 0.f;
#pragma unroll
            for (int nt = 0; nt < 8; ++nt) {
                s[nt][0] = __expf(s[nt][0] - m0); sum0 += s[nt][0];
                s[nt][1] = __expf(s[nt][1] - m0); sum0 += s[nt][1];
                s[nt][2] = __expf(s[nt][2] - m1); sum1 += s[nt][2];
                s[nt][3] = __expf(s[nt][3] - m1); sum1 += s[nt][3];
            }
            l0 = l0 * cor0 + sum0;
            l1 = l1 * cor1 + sum1;
#pragma unroll
            for (int i = 0; i < 16; ++i) {
                o[i][0] *= cor0; o[i][1] *= cor0;
                o[i][2] *= cor1; o[i][3] *= cor1;
            }

            uint32_t ph[4][4], pl[4][4];
#pragma unroll
            for (int ks = 0; ks < 4; ++ks) {
                pack_hilo_f16(s[2 * ks][0],     s[2 * ks][1],     ph[ks][0], pl[ks][0]);
                pack_hilo_f16(s[2 * ks][2],     s[2 * ks][3],     ph[ks][1], pl[ks][1]);
                pack_hilo_f16(s[2 * ks + 1][0], s[2 * ks + 1][1], ph[ks][2], pl[ks][2]);
                pack_hilo_f16(s[2 * ks + 1][2], s[2 * ks + 1][3], ph[ks][3], pl[ks][3]);
            }

#pragma unroll
            for (int ks = 0; ks < 4; ++ks) {
#pragma unroll
                for (int dt2 = 0; dt2 < 8; ++dt2) {
                    uint32_t va = (uint32_t)(16 * ks + rv) * 256u
                                + (uint32_t)(((2 * dt2 + cv) ^ (rv & 7)) << 4);
                    uint32_t bv[4];
                    ldsm4t(bv, Vb + va);
                    mma16816h(o[2 * dt2], ph[ks], bv);
                    mma16816h(o[2 * dt2], pl[ks], bv);
                    mma16816h(o[2 * dt2 + 1], ph[ks], bv + 2);
                    mma16816h(o[2 * dt2 + 1], pl[ks], bv + 2);
                }
            }
        }
        __syncthreads();
    }

    l0 += __shfl_xor_sync(0xffffffffu, l0, 1);
    l0 += __shfl_xor_sync(0xffffffffu, l0, 2);
    l1 += __shfl_xor_sync(0xffffffffu, l1, 1);
    l1 += __shfl_xor_sync(0xffffffffu, l1, 2);
    float inv0 = 1.f / l0, inv1 = 1.f / l1;

    const int h = g * GQ + wh;
    const int t0r = T0 + wtt + (lane >> 2);
#pragma unroll
    for (int nt = 0; nt < 16; ++nt) {
        int col = h * DH + nt * 8 + 2 * (lane & 3);
        float2 a = make_float2(o[nt][0] * inv0, o[nt][1] * inv0);
        float2 b = make_float2(o[nt][2] * inv1, o[nt][3] * inv1);
        *(float2*)&g_og[(size_t)t0r * HID + col] = a;
        *(float2*)&g_og[(size_t)(t0r + 8) * HID + col] = b;
    }
}

// ================= MMA local band attention + gate combine ====================
#define LOCAL_SMEM 98304   // Q 32KB + K 32KB + V 32KB

__global__ void __launch_bounds__(128, 1) local_mma(
    const __half* __restrict__ qh_g, const __half* __restrict__ ql_g,
    const __half* __restrict__ k_g, const __half* __restrict__ v_g)
{
    extern __shared__ char smem[];
    const uint32_t sb = smem_u32(smem);
    const int tid = threadIdx.x, wid = tid >> 5, lane = tid & 31;
    const int h = blockIdx.y, g = h >> 2;
    const int T0 = blockIdx.x * 64;
    const int S0 = T0 - 64;

    const uint32_t QH = sb, QL = sb + 16384u;
    const uint32_t Kb = sb + 32768u, Vb = sb + 65536u;

#pragma unroll
    for (int j = 0; j < 8; ++j) {
        int slot = tid + j * 128;
        int row = slot >> 4;
        int ch = slot & 15;
        uint32_t off = (uint32_t)row * 256u + (uint32_t)((ch ^ (row & 7)) << 4);
        size_t gi = ((size_t)(T0 + row) * NH + h) * DH + ch * 8;
        cpa16(QH + off, qh_g + gi);
        cpa16(QL + off, ql_g + gi);
    }
#pragma unroll
    for (int j = 0; j < 16; ++j) {
        int slot = tid + j * 128;
        int row = slot >> 4;
        int ch = slot & 15;
        uint32_t off = (uint32_t)row * 256u + (uint32_t)((ch ^ (row & 7)) << 4);
        int srow = S0 + row;
        if (srow < 0) srow = 0;
        size_t gi = ((size_t)srow * NKV + g) * DH + ch * 8;
        cpa16(Kb + off, k_g + gi);
        cpa16(Vb + off, v_g + gi);
    }
    CP_COMMIT();
    CP_WAIT(0);
    __syncthreads();

    const int mrow = wid * 16;
    const int rq = mrow + (lane & 15);
    const uint32_t qbase = (uint32_t)rq * 256u;
    const int cq = lane >> 4;
    const int rk = (lane & 7) | ((lane & 16) >> 1);
    const int ck = (lane >> 3) & 1;
    const int rv = lane & 15;
    const int cv = lane >> 4;

    float s[16][4];
#pragma unroll
    for (int i = 0; i < 16; ++i)
#pragma unroll
        for (int j = 0; j < 4; ++j) s[i][j] = 0.f;

#pragma unroll
    for (int k = 0; k < 8; ++k) {
        uint32_t qa = qbase + (uint32_t)((((2 * k + cq) ^ (rq & 7))) << 4);
        uint32_t aqh[4], aql[4];
        ldsm4(aqh, QH + qa);
        ldsm4(aql, QL + qa);
#pragma unroll
        for (int nt2 = 0; nt2 < 8; ++nt2) {
            uint32_t ka = (uint32_t)(nt2 * 16 + rk) * 256u
                        + (uint32_t)(((2 * k + ck) ^ (rk & 7)) << 4);
            uint32_t bk[4];
            ldsm4(bk, Kb + ka);
            mma16816h(s[2 * nt2], aqh, bk);
            mma16816h(s[2 * nt2], aql, bk);
            mma16816h(s[2 * nt2 + 1], aqh, bk + 2);
            mma16816h(s[2 * nt2 + 1], aql, bk + 2);
        }
    }

    const int tr0 = T0 + mrow + (lane >> 2);
    const int tr1 = tr0 + 8;
#pragma unroll
    for (int nt = 0; nt < 16; ++nt) {
        int c0 = S0 + nt * 8 + 2 * (lane & 3);
        int c1 = c0 + 1;
        if (c0 > tr0 || c0 < tr0 - 63 || c0 < 0) s[nt][0] = -1e9f;
        if (c1 > tr0 || c1 < tr0 - 63 || c1 < 0) s[nt][1] = -1e9f;
        if (c0 > tr1 || c0 < tr1 - 63 || c0 < 0) s[nt][2] = -1e9f;
        if (c1 > tr1 || c1 < tr1 - 63 || c1 < 0) s[nt][3] = -1e9f;
    }

    float mx0 = -1e30f, mx1 = -1e30f;
#pragma unroll
    for (int nt = 0; nt < 16; ++nt) {
        mx0 = fmaxf(mx0, fmaxf(s[nt][0], s[nt][1]));
        mx1 = fmaxf(mx1, fmaxf(s[nt][2], s[nt][3]));
    }
    mx0 = fmaxf(mx0, __shfl_xor_sync(0xffffffffu, mx0, 1));
    mx0 = fmaxf(mx0, __shfl_xor_sync(0xffffffffu, mx0, 2));
    mx1 = fmaxf(mx1, __shfl_xor_sync(0xffffffffu, mx1, 1));
    mx1 = fmaxf(mx1, __shfl_xor_sync(0xffffffffu, mx1, 2));

    float l0 = 0.f, l1 = 0.f;
#pragma unroll
    for (int nt = 0; nt < 16; ++nt) {
        s[nt][0] = __expf(s[nt][0] - mx0); l0 += s[nt][0];
        s[nt][1] = __expf(s[nt][1] - mx0); l0 += s[nt][1];
        s[nt][2] = __expf(s[nt][2] - mx1); l1 += s[nt][2];
        s[nt][3] = __expf(s[nt][3] - mx1); l1 += s[nt][3];
    }
    l0 += __shfl_xor_sync(0xffffffffu, l0, 1);
    l0 += __shfl_xor_sync(0xffffffffu, l0, 2);
    l1 += __shfl_xor_sync(0xffffffffu, l1, 1);
    l1 += __shfl_xor_sync(0xffffffffu, l1, 2);

    float o[16][4];
#pragma unroll
    for (int i = 0; i < 16; ++i)
#pragma unroll
        for (int j = 0; j < 4; ++j) o[i][j] = 0.f;

#pragma unroll
    for (int ks = 0; ks < 8; ++ks) {
        uint32_t ph[4], pl[4];
        pack_hilo_f16(s[2 * ks][0],     s[2 * ks][1],     ph[0], pl[0]);
        pack_hilo_f16(s[2 * ks][2],     s[2 * ks][3],     ph[1], pl[1]);
        pack_hilo_f16(s[2 * ks + 1][0], s[2 * ks + 1][1], ph[2], pl[2]);
        pack_hilo_f16(s[2 * ks + 1][2], s[2 * ks + 1][3], ph[3], pl[3]);
#pragma unroll
        for (int dt2 = 0; dt2 < 8; ++dt2) {
            uint32_t va = (uint32_t)(16 * ks + rv) * 256u
                        + (uint32_t)(((2 * dt2 + cv) ^ (rv & 7)) << 4);
            uint32_t bv[4];
            ldsm4t(bv, Vb + va);
            mma16816h(o[2 * dt2], ph, bv);
            mma16816h(o[2 * dt2], pl, bv);
            mma16816h(o[2 * dt2 + 1], ph, bv + 2);
            mma16816h(o[2 * dt2 + 1], pl, bv + 2);
        }
    }

    const float inv0 = 1.f / l0, inv1 = 1.f / l1;
    const int r0 = tr0;
    const float gt0 = g_gate[r0 * NH + h];
    const float gt1 = g_gate[(r0 + 8) * NH + h];
    const float ng0 = 1.f - gt0, ng1 = 1.f - gt1;

#pragma unroll
    for (int nt = 0; nt < 16; ++nt) {
        int col = h * DH + nt * 8 + 2 * (lane & 3);
        float2 ga = *(float2*)&g_og[(size_t)r0 * HID + col];
        float2 gb = *(float2*)&g_og[(size_t)(r0 + 8) * HID + col];
        float a0 = ga.x * gt0 + o[nt][0] * inv0 * ng0;
        float a1 = ga.y * gt0 + o[nt][1] * inv0 * ng0;
        float b0 = gb.x * gt1 + o[nt][2] * inv1 * ng1;
        float b1 = gb.y * gt1 + o[nt][3] * inv1 * ng1;
        *(uint32_t*)&g_og16[(size_t)r0 * HID + col] = pack_f16x2(a0, a1);
        *(uint32_t*)&g_og16[(size_t)(r0 + 8) * HID + col] = pack_f16x2(b0, b1);
    }
}

// ---------------- launch --------------------------------------------------------
extern "C" void kernel_launch(void* const* d_in, const int* in_sizes, int n_in,
                              void* d_out, int out_size)
{
    const int*   positions = (const int*)d_in[0];
    const float* hidden    = (const float*)d_in[1];
    const float* k_global  = (const float*)d_in[2];
    const float* v_global  = (const float*)d_in[3];
    const float* w_qkv     = (const float*)d_in[4];
    const float* w_o       = (const float*)d_in[5];
    const float* w_gate    = (const float*)d_in[6];
    const float* b_gate    = (const float*)d_in[7];
    float* out = (float*)d_out;

    float* qkv = nullptr; cudaGetSymbolAddress((void**)&qkv, g_qkv);
    __half *hid16, *wqkv16, *wo16, *og16;
    __half *q_hi, *q_lo, *k16, *v16, *kl16, *vl16;
    cudaGetSymbolAddress((void**)&hid16,   g_hid16);
    cudaGetSymbolAddress((void**)&wqkv16,  g_wqkv16);
    cudaGetSymbolAddress((void**)&wo16,    g_wo16);
    cudaGetSymbolAddress((void**)&og16,    g_og16);
    cudaGetSymbolAddress((void**)&q_hi,    g_q_hi);
    cudaGetSymbolAddress((void**)&q_lo,    g_q_lo);
    cudaGetSymbolAddress((void**)&k16,     g_k16);
    cudaGetSymbolAddress((void**)&v16,     g_v16);
    cudaGetSymbolAddress((void**)&kl16,    g_kl16);
    cudaGetSymbolAddress((void**)&vl16,    g_vl16);

    cudaFuncSetAttribute(gemm_f16, cudaFuncAttributeMaxDynamicSharedMemorySize,
                         GEMM_SMEM);
    cudaFuncSetAttribute(attn_mma, cudaFuncAttributeMaxDynamicSharedMemorySize,
                         ATTN_SMEM);
    cudaFuncSetAttribute(local_mma, cudaFuncAttributeMaxDynamicSharedMemorySize,
                         LOCAL_SMEM);

    build_trig_kernel<<<(T_SEQ * 64 + 255) / 256, 256>>>(positions);

    int n4_hid  = T_SEQ * HID / 4;
    int n4_wqkv = QKV_W * HID / 4;
    int n4_wo   = HID * HID / 4;
    int n4_kv   = T_SEQ * NKV * DH / 4;
    cvt_f16<<<(n4_hid  + 255) / 256, 256>>>(hidden, hid16, n4_hid);
    cvt_f16<<<(n4_wqkv + 255) / 256, 256>>>(w_qkv, wqkv16, n4_wqkv);
    cvt_f16<<<(n4_wo   + 255) / 256, 256>>>(w_o, wo16, n4_wo);
    cvt_f16<<<(n4_kv   + 255) / 256, 256>>>(k_global, k16, n4_kv);
    cvt_f16<<<(n4_kv   + 255) / 256, 256>>>(v_global, v16, n4_kv);

    gemm_f16<<<dim3(QKV_W / 128, T_SEQ / 256), 512, GEMM_SMEM>>>(
        hid16, wqkv16, qkv, T_SEQ, QKV_W, HID);

    rope_gate_kernel<<<T_SEQ, 256>>>(w_gate, b_gate);

    attn_mma<<<dim3(T_SEQ / 32, NKV), 256, ATTN_SMEM>>>(
        q_hi, q_lo, k16, v16);

    local_mma<<<dim3(T_SEQ / 64, NH), 128, LOCAL_SMEM>>>(
        q_hi, q_lo, kl16, vl16);

    gemm_f16<<<dim3(HID / 128, T_SEQ / 256), 512, GEMM_SMEM>>>(
        og16, wo16, out, T_SEQ, HID, HID);
}

// round 16
// speedup vs baseline: 2.2623x; 2.2623x over previous
#include <cuda_runtime.h>
#include <cuda_bf16.h>
#include <cuda_fp16.h>
#include <math.h>
#include <stdint.h>

#define T_SEQ 2048
#define HID   4096
#define NH    32
#define NKV   8
#define GQ    4
#define DH    128
#define WIN   64
#define QKV_W 6144
#define SCALE 0.08838834764831845f

// ---------------- scratch ---------------------------------------------------
__device__ float g_qkv[(size_t)T_SEQ * QKV_W];
__device__ float g_og[(size_t)T_SEQ * HID];     // global attn out (fp32)
__device__ float g_gate[T_SEQ * NH];
__device__ float g_cosT[T_SEQ * 64];
__device__ float g_sinT[T_SEQ * 64];

// fp16 GEMM operands (symmetric single-fp16)
__device__ __half g_hid16[(size_t)T_SEQ * HID];
__device__ __half g_wqkv16[(size_t)QKV_W * HID];
__device__ __half g_wo16[(size_t)HID * HID];
__device__ __half g_og16[(size_t)T_SEQ * HID];   // gated combined out

// attention operands: Q fp16 hi/lo (scaled), K/V single fp16
__device__ __half g_q_hi[(size_t)T_SEQ * NH * DH];
__device__ __half g_q_lo[(size_t)T_SEQ * NH * DH];
__device__ __half g_k16[(size_t)T_SEQ * NKV * DH];
__device__ __half g_v16[(size_t)T_SEQ * NKV * DH];
// local-window k/v (post-rope, from qkv projection), single fp16
__device__ __half g_kl16[(size_t)T_SEQ * NKV * DH];
__device__ __half g_vl16[(size_t)T_SEQ * NKV * DH];

// ================= low-level helpers =========================================
__device__ __forceinline__ uint32_t smem_u32(const void* p) {
    uint32_t a;
    asm("{ .reg .u64 t; cvta.to.shared.u64 t, %1; cvt.u32.u64 %0, t; }"
        : "=r"(a) : "l"(p));
    return a;
}
__device__ __forceinline__ void cpa16(uint32_t dst, const void* src) {
    asm volatile("cp.async.cg.shared.global [%0], [%1], 16;"
                 :: "r"(dst), "l"(src) : "memory");
}
#define CP_COMMIT() asm volatile("cp.async.commit_group;" ::: "memory")
#define CP_WAIT(n)  asm volatile("cp.async.wait_group %0;" :: "n"(n) : "memory")

__device__ __forceinline__ void ldsm4(uint32_t* r, uint32_t addr) {
    asm volatile("ldmatrix.sync.aligned.m8n8.x4.shared.b16 {%0,%1,%2,%3}, [%4];"
                 : "=r"(r[0]), "=r"(r[1]), "=r"(r[2]), "=r"(r[3]) : "r"(addr));
}
__device__ __forceinline__ void ldsm4t(uint32_t* r, uint32_t addr) {
    asm volatile("ldmatrix.sync.aligned.m8n8.x4.trans.shared.b16 {%0,%1,%2,%3}, [%4];"
                 : "=r"(r[0]), "=r"(r[1]), "=r"(r[2]), "=r"(r[3]) : "r"(addr));
}
__device__ __forceinline__ void mma16816h(float* d, const uint32_t* a,
                                          const uint32_t* b) {
    asm volatile(
        "mma.sync.aligned.m16n8k16.row.col.f32.f16.f16.f32 "
        "{%0,%1,%2,%3}, {%4,%5,%6,%7}, {%8,%9}, {%0,%1,%2,%3};"
        : "+f"(d[0]), "+f"(d[1]), "+f"(d[2]), "+f"(d[3])
        : "r"(a[0]), "r"(a[1]), "r"(a[2]), "r"(a[3]), "r"(b[0]), "r"(b[1]));
}
__device__ __forceinline__ uint32_t pack_f16x2(float x, float y) {
    __half2 h = __floats2half2_rn(x, y);
    return *(uint32_t*)&h;
}
__device__ __forceinline__ void pack_hilo_f16(float x, float y,
                                              uint32_t& hi, uint32_t& lo) {
    __half hx = __float2half_rn(x), hy = __float2half_rn(y);
    float rx = x - __half2float(hx), ry = y - __half2float(hy);
    __half lx = __float2half_rn(rx), ly = __float2half_rn(ry);
    hi = (uint32_t)__half_as_ushort(hx) | ((uint32_t)__half_as_ushort(hy) << 16);
    lo = (uint32_t)__half_as_ushort(lx) | ((uint32_t)__half_as_ushort(ly) << 16);
}

// ---------------- trig table -------------------------------------------------
__global__ void build_trig_kernel(const int* __restrict__ positions) {
    int i = blockIdx.x * blockDim.x + threadIdx.x;
    if (i >= T_SEQ * 64) return;
    int t = i >> 6, d = i & 63;
    double inv = pow(10000.0, -(double)d / 64.0);
    double ang = (double)positions[t] * inv;
    g_cosT[i] = (float)cos(ang);
    g_sinT[i] = (float)sin(ang);
}

// ---------------- fp32 -> fp16 single ------------------------------------------
__global__ void __launch_bounds__(256) cvt_f16(
    const float* __restrict__ x, __half* __restrict__ y, int n4)
{
    int i = blockIdx.x * blockDim.x + threadIdx.x;
    if (i >= n4) return;
    float4 v = ((const float4*)x)[i];
    uint2 o;
    o.x = pack_f16x2(v.x, v.y);
    o.y = pack_f16x2(v.z, v.w);
    ((uint2*)y)[i] = o;
}

// ====== symmetric fp16 MMA GEMM: C[M,N] = A16[M,K] * B16[N,K]^T ===============
// 256x128 CTA tile, 512 threads, 16 warps (4M x 4N), 64x32 warp tiles.
// __launch_bounds__(512, 1): regs cap 128 (need ~100, no spill).
#define STAGES 2
#define STG_B  24576                 // A 16KB + B 8KB
#define GEMM_SMEM (STAGES * STG_B)

__device__ __forceinline__ void load_stage(
    uint32_t sbase, int stage, int c,
    const __half* __restrict__ A, const __half* __restrict__ B,
    int bm, int bn, int K, int tid)
{
    const int k0 = c * 32;
    const uint32_t st = sbase + stage * STG_B;
#pragma unroll
    for (int j = 0; j < 3; ++j) {
        int l = tid + j * 512;            // 0..1535
        const bool isB = (j == 2);        // compile-time per j
        int li = isB ? (l - 1024) : l;    // A: 0..1023, B: 0..511
        int row = li >> 2;
        int ch = li & 3;
        uint32_t dst = st + (isB ? 16384u : 0u) + (uint32_t)row * 64u
                     + (uint32_t)((ch ^ ((row >> 1) & 3)) << 4);
        const __half* src = isB
            ? B + (size_t)(bn + row) * K + k0 + ch * 8
            : A + (size_t)(bm + row) * K + k0 + ch * 8;
        cpa16(dst, src);
    }
}

__global__ void __launch_bounds__(512, 1) gemm_f16(
    const __half* __restrict__ A, const __half* __restrict__ B,
    float* __restrict__ C, int M, int N, int K)
{
    extern __shared__ char smem[];
    const uint32_t sbase = smem_u32(smem);
    const int tid = threadIdx.x;
    const int wid = tid >> 5, lane = tid & 31;
    const int bm = blockIdx.y * 256, bn = blockIdx.x * 128;
    const int wm = (wid & 3) * 64;      // warp M band (64 rows)
    const int wn = (wid >> 2) * 32;     // warp N band (32 cols)

    float acc[4][4][4];
#pragma unroll
    for (int mi = 0; mi < 4; ++mi)
#pragma unroll
        for (int ni = 0; ni < 4; ++ni)
#pragma unroll
            for (int k = 0; k < 4; ++k) acc[mi][ni][k] = 0.f;

    const int nch = K / 32;

    load_stage(sbase, 0, 0, A, B, bm, bn, K, tid);
    CP_COMMIT();

    uint32_t offA[4], offB[2];
    int swA[4], swB[2];
#pragma unroll
    for (int mi = 0; mi < 4; ++mi) {
        int row = wm + mi * 16 + (lane & 15);
        offA[mi] = (uint32_t)row * 64u;
        swA[mi] = (row >> 1) & 3;
    }
#pragma unroll
    for (int nj = 0; nj < 2; ++nj) {
        int row = wn + nj * 16 + ((lane >> 4) << 3) + (lane & 7);
        offB[nj] = (uint32_t)row * 64u;
        swB[nj] = (row >> 1) & 3;
    }
    const int chA = (lane >> 4);
    const int chB = ((lane >> 3) & 1);

    for (int c = 0; c < nch; ++c) {
        CP_WAIT(0);
        __syncthreads();
        if (c + 1 < nch)
            load_stage(sbase, (c + 1) & 1, c + 1, A, B, bm, bn, K, tid);
        CP_COMMIT();

        const uint32_t st = sbase + (uint32_t)(c & 1) * STG_B;
#pragma unroll
        for (int ks = 0; ks < 2; ++ks) {
            uint32_t ra[4][4], rb[2][4];
#pragma unroll
            for (int mi = 0; mi < 4; ++mi) {
                int ch = ks * 2 + chA;
                uint32_t o = offA[mi] + (uint32_t)((ch ^ swA[mi]) << 4);
                ldsm4(ra[mi], st + o);
            }
#pragma unroll
            for (int nj = 0; nj < 2; ++nj) {
                int ch = ks * 2 + chB;
                uint32_t o = offB[nj] + (uint32_t)((ch ^ swB[nj]) << 4);
                ldsm4(rb[nj], st + 16384u + o);
            }
#pragma unroll
            for (int mi = 0; mi < 4; ++mi)
#pragma unroll
                for (int ni = 0; ni < 4; ++ni) {
                    const uint32_t* b2 = &rb[ni >> 1][(ni & 1) * 2];
                    mma16816h(acc[mi][ni], ra[mi], b2);
                }
        }
        __syncthreads();
    }

    const int g = lane >> 2, q = lane & 3;
#pragma unroll
    for (int mi = 0; mi < 4; ++mi)
#pragma unroll
        for (int ni = 0; ni < 4; ++ni) {
            int r0 = bm + wm + mi * 16 + g;
            int col = bn + wn + ni * 8 + q * 2;
            float2 v0 = make_float2(acc[mi][ni][0], acc[mi][ni][1]);
            float2 v1 = make_float2(acc[mi][ni][2], acc[mi][ni][3]);
            *(float2*)(C + (size_t)r0 * N + col) = v0;
            *(float2*)(C + (size_t)(r0 + 8) * N + col) = v1;
        }
}

// ---------------- RoPE + gate + fp16 exports ------------------------------------
__global__ void __launch_bounds__(256) rope_gate_kernel(
    const float* __restrict__ w_gate, const float* __restrict__ b_gate)
{
    int t = blockIdx.x;
    float* row = g_qkv + (size_t)t * QKV_W;

    for (int idx = threadIdx.x; idx < 48 * 64; idx += 256) {
        int head = idx >> 6;
        int d = idx & 63;
        if (head < NH) {                       // q heads: rope + scaled fp16 hi/lo
            int base = head * DH;
            float c = g_cosT[t * 64 + d];
            float s = g_sinT[t * 64 + d];
            float x1 = row[base + d];
            float x2 = row[base + d + 64];
            float y1 = x1 * c - x2 * s;
            float y2 = x2 * c + x1 * s;
            row[base + d]      = y1;           // for gate
            row[base + d + 64] = y2;
            size_t qi = ((size_t)t * NH + head) * DH + d;
            float a1 = y1 * SCALE, a2 = y2 * SCALE;
            __half h1 = __float2half_rn(a1);
            __half h2 = __float2half_rn(a2);
            g_q_hi[qi]      = h1;
            g_q_hi[qi + 64] = h2;
            g_q_lo[qi]      = __float2half_rn(a1 - __half2float(h1));
            g_q_lo[qi + 64] = __float2half_rn(a2 - __half2float(h2));
        } else if (head < NH + NKV) {          // k heads: rope + single fp16
            int gk = head - NH;
            int base = HID + gk * DH;
            float c = g_cosT[t * 64 + d];
            float s = g_sinT[t * 64 + d];
            float x1 = row[base + d];
            float x2 = row[base + d + 64];
            float y1 = x1 * c - x2 * s;
            float y2 = x2 * c + x1 * s;
            size_t ki = ((size_t)t * NKV + gk) * DH + d;
            g_kl16[ki]      = __float2half_rn(y1);
            g_kl16[ki + 64] = __float2half_rn(y2);
        } else {                               // v heads: single fp16
            int gv = head - NH - NKV;
            int base = HID + NKV * DH + gv * DH;
            size_t vi = ((size_t)t * NKV + gv) * DH + d;
            g_vl16[vi]      = __float2half_rn(row[base + d]);
            g_vl16[vi + 64] = __float2half_rn(row[base + d + 64]);
        }
    }
    __syncthreads();

    int wid = threadIdx.x >> 5, lane = threadIdx.x & 31;
    for (int h = wid; h < NH; h += 8) {
        const float* q = row + h * DH;
        const float* w = w_gate + h * DH;
        float acc = q[lane] * w[lane] + q[lane + 32] * w[lane + 32]
                  + q[lane + 64] * w[lane + 64] + q[lane + 96] * w[lane + 96];
#pragma unroll
        for (int off = 16; off; off >>= 1)
            acc += __shfl_xor_sync(0xffffffffu, acc, off);
        if (lane == 0)
            g_gate[t * NH + h] = 1.f / (1.f + __expf(-(acc + b_gate[h])));
    }
}

// ================= MMA flash attention (global causal, GQA-shared KV) =========
#define ATTN_SMEM 131072   // Q 64KB + 2 x (K 16KB + V 16KB)

__device__ __forceinline__ void attn_load_kv(
    uint32_t buf, int s0, int g, int tid,
    const __half* k16, const __half* v16)
{
#pragma unroll
    for (int j = 0; j < 4; ++j) {
        int slot = tid + j * 256;
        int row = slot >> 4;
        int ch = slot & 15;
        uint32_t off = (uint32_t)row * 256u + (uint32_t)((ch ^ (row & 7)) << 4);
        size_t gi = ((size_t)(s0 + row) * NKV + g) * DH + ch * 8;
        cpa16(buf + off, k16 + gi);
        cpa16(buf + 16384u + off, v16 + gi);
    }
}

__global__ void __launch_bounds__(256, 1) attn_mma(
    const __half* __restrict__ qh_g, const __half* __restrict__ ql_g,
    const __half* __restrict__ k_g, const __half* __restrict__ v_g)
{
    extern __shared__ char smem[];
    const uint32_t sb = smem_u32(smem);
    const int tid = threadIdx.x, wid = tid >> 5, lane = tid & 31;
    const int g = blockIdx.y;
    const int T0 = (gridDim.x - 1 - blockIdx.x) * 32;   // heavy blocks first
    const int nblk = (T0 + 32 + 63) / 64;

    const uint32_t QH = sb, QL = sb + 32768u;
    const uint32_t KV0 = sb + 65536u;

#pragma unroll
    for (int j = 0; j < 8; ++j) {
        int slot = tid + j * 256;
        int row = slot >> 4;               // 0..127
        int ch = slot & 15;
        uint32_t off = (uint32_t)row * 256u + (uint32_t)((ch ^ (row & 7)) << 4);
        int tt = row & 31;
        int hi = row >> 5;
        size_t gi = ((size_t)(T0 + tt) * NH + (g * GQ + hi)) * DH + ch * 8;
        cpa16(QH + off, qh_g + gi);
        cpa16(QL + off, ql_g + gi);
    }
    attn_load_kv(KV0, 0, g, tid, k_g, v_g);
    CP_COMMIT();

    const int mrow = wid * 16;
    const int rq = mrow + (lane & 15);
    const uint32_t qbase = (uint32_t)rq * 256u;
    const int cq = lane >> 4;
    const int rk = (lane & 7) | ((lane & 16) >> 1);
    const int ck = (lane >> 3) & 1;
    const int rv = lane & 15;
    const int cv = lane >> 4;
    const int wh = mrow >> 5;
    const int wtt = mrow & 31;

    float o[16][4];
#pragma unroll
    for (int i = 0; i < 16; ++i)
#pragma unroll
        for (int j = 0; j < 4; ++j) o[i][j] = 0.f;
    float m0 = -1e30f, m1 = -1e30f, l0 = 0.f, l1 = 0.f;

    for (int blk = 0; blk < nblk; ++blk) {
        if (blk + 1 < nblk)
            attn_load_kv(KV0 + (uint32_t)((blk + 1) & 1) * 32768u,
                         (blk + 1) * 64, g, tid, k_g, v_g);
        CP_COMMIT();
        CP_WAIT(1);
        __syncthreads();

        const int s0 = blk * 64;
        const bool active = (s0 <= T0 + wtt + 15);
        if (active) {
            const uint32_t buf = KV0 + (uint32_t)(blk & 1) * 32768u;
            const uint32_t Kb = buf, Vb = buf + 16384u;

            float s[8][4];
#pragma unroll
            for (int i = 0; i < 8; ++i)
#pragma unroll
                for (int j = 0; j < 4; ++j) s[i][j] = 0.f;

#pragma unroll
            for (int k = 0; k < 8; ++k) {
                uint32_t qa = qbase + (uint32_t)((((2 * k + cq) ^ (rq & 7))) << 4);
                uint32_t aqh[4], aql[4];
                ldsm4(aqh, QH + qa);
                ldsm4(aql, QL + qa);
#pragma unroll
                for (int nt2 = 0; nt2 < 4; ++nt2) {
                    uint32_t ka = (uint32_t)(nt2 * 16 + rk) * 256u
                                + (uint32_t)(((2 * k + ck) ^ (rk & 7)) << 4);
                    uint32_t bk[4];
                    ldsm4(bk, Kb + ka);
                    mma16816h(s[2 * nt2], aqh, bk);
                    mma16816h(s[2 * nt2], aql, bk);
                    mma16816h(s[2 * nt2 + 1], aqh, bk + 2);
                    mma16816h(s[2 * nt2 + 1], aql, bk + 2);
                }
            }

            if (s0 + 63 > T0 + wtt) {
                const int tr0 = T0 + wtt + (lane >> 2);
                const int tr1 = tr0 + 8;
#pragma unroll
                for (int nt = 0; nt < 8; ++nt) {
                    int sc = s0 + nt * 8 + 2 * (lane & 3);
                    if (sc > tr0)     s[nt][0] = -1e9f;
                    if (sc + 1 > tr0) s[nt][1] = -1e9f;
                    if (sc > tr1)     s[nt][2] = -1e9f;
                    if (sc + 1 > tr1) s[nt][3] = -1e9f;
                }
            }

            float mx0 = -1e30f, mx1 = -1e30f;
#pragma unroll
            for (int nt = 0; nt < 8; ++nt) {
                mx0 = fmaxf(mx0, fmaxf(s[nt][0], s[nt][1]));
                mx1 = fmaxf(mx1, fmaxf(s[nt][2], s[nt][3]));
            }
            mx0 = fmaxf(mx0, __shfl_xor_sync(0xffffffffu, mx0, 1));
            mx0 = fmaxf(mx0, __shfl_xor_sync(0xffffffffu, mx0, 2));
            mx1 = fmaxf(mx1, __shfl_xor_sync(0xffffffffu, mx1, 1));
            mx1 = fmaxf(mx1, __shfl_xor_sync(0xffffffffu, mx1, 2));
            float nm0 = fmaxf(m0, mx0), nm1 = fmaxf(m1, mx1);
            float cor0 = __expf(m0 - nm0), cor1 = __expf(m1 - nm1);
            m0 = nm0; m1 = nm1;

            float sum0 = 0.f, sum1 = 0.f;
#pragma unroll
            for (int nt = 0; nt < 8; ++nt) {
                s[nt][0] = __expf(s[nt][0] - m0); sum0 += s[nt][0];
                s[nt][1] = __expf(s[nt][1] - m0); sum0 += s[nt][1];
                s[nt][2] = __expf(s[nt][2] - m1); sum1 += s[nt][2];
                s[nt][3] = __expf(s[nt][3] - m1); sum1 += s[nt][3];
            }
            l0 = l0 * cor0 + sum0;
            l1 = l1 * cor1 + sum1;
#pragma unroll
            for (int i = 0; i < 16; ++i) {
                o[i][0] *= cor0; o[i][1] *= cor0;
                o[i][2] *= cor1; o[i][3] *= cor1;
            }

            uint32_t ph[4][4], pl[4][4];
#pragma unroll
            for (int ks = 0; ks < 4; ++ks) {
                pack_hilo_f16(s[2 * ks][0],     s[2 * ks][1],     ph[ks][0], pl[ks][0]);
                pack_hilo_f16(s[2 * ks][2],     s[2 * ks][3],     ph[ks][1], pl[ks][1]);
                pack_hilo_f16(s[2 * ks + 1][0], s[2 * ks + 1][1], ph[ks][2], pl[ks][2]);
                pack_hilo_f16(s[2 * ks + 1][2], s[2 * ks + 1][3], ph[ks][3], pl[ks][3]);
            }

#pragma unroll
            for (int ks = 0; ks < 4; ++ks) {
#pragma unroll
                for (int dt2 = 0; dt2 < 8; ++dt2) {
                    uint32_t va = (uint32_t)(16 * ks + rv) * 256u
                                + (uint32_t)(((2 * dt2 + cv) ^ (rv & 7)) << 4);
                    uint32_t bv[4];
                    ldsm4t(bv, Vb + va);
                    mma16816h(o[2 * dt2], ph[ks], bv);
                    mma16816h(o[2 * dt2], pl[ks], bv);
                    mma16816h(o[2 * dt2 + 1], ph[ks], bv + 2);
                    mma16816h(o[2 * dt2 + 1], pl[ks], bv + 2);
                }
            }
        }
        __syncthreads();
    }

    l0 += __shfl_xor_sync(0xffffffffu, l0, 1);
    l0 += __shfl_xor_sync(0xffffffffu, l0, 2);
    l1 += __shfl_xor_sync(0xffffffffu, l1, 1);
    l1 += __shfl_xor_sync(0xffffffffu, l1, 2);
    float inv0 = 1.f / l0, inv1 = 1.f / l1;

    const int h = g * GQ + wh;
    const int t0r = T0 + wtt + (lane >> 2);
#pragma unroll
    for (int nt = 0; nt < 16; ++nt) {
        int col = h * DH + nt * 8 + 2 * (lane & 3);
        float2 a = make_float2(o[nt][0] * inv0, o[nt][1] * inv0);
        float2 b = make_float2(o[nt][2] * inv1, o[nt][3] * inv1);
        *(float2*)&g_og[(size_t)t0r * HID + col] = a;
        *(float2*)&g_og[(size_t)(t0r + 8) * HID + col] = b;
    }
}

// ================= MMA local band attention + gate combine ====================
#define LOCAL_SMEM 98304   // Q 32KB + K 32KB + V 32KB

__global__ void __launch_bounds__(128, 1) local_mma(
    const __half* __restrict__ qh_g, const __half* __restrict__ ql_g,
    const __half* __restrict__ k_g, const __half* __restrict__ v_g)
{
    extern __shared__ char smem[];
    const uint32_t sb = smem_u32(smem);
    const int tid = threadIdx.x, wid = tid >> 5, lane = tid & 31;
    const int h = blockIdx.y, g = h >> 2;
    const int T0 = blockIdx.x * 64;
    const int S0 = T0 - 64;

    const uint32_t QH = sb, QL = sb + 16384u;
    const uint32_t Kb = sb + 32768u, Vb = sb + 65536u;

#pragma unroll
    for (int j = 0; j < 8; ++j) {
        int slot = tid + j * 128;
        int row = slot >> 4;
        int ch = slot & 15;
        uint32_t off = (uint32_t)row * 256u + (uint32_t)((ch ^ (row & 7)) << 4);
        size_t gi = ((size_t)(T0 + row) * NH + h) * DH + ch * 8;
        cpa16(QH + off, qh_g + gi);
        cpa16(QL + off, ql_g + gi);
    }
#pragma unroll
    for (int j = 0; j < 16; ++j) {
        int slot = tid + j * 128;
        int row = slot >> 4;
        int ch = slot & 15;
        uint32_t off = (uint32_t)row * 256u + (uint32_t)((ch ^ (row & 7)) << 4);
        int srow = S0 + row;
        if (srow < 0) srow = 0;
        size_t gi = ((size_t)srow * NKV + g) * DH + ch * 8;
        cpa16(Kb + off, k_g + gi);
        cpa16(Vb + off, v_g + gi);
    }
    CP_COMMIT();
    CP_WAIT(0);
    __syncthreads();

    const int mrow = wid * 16;
    const int rq = mrow + (lane & 15);
    const uint32_t qbase = (uint32_t)rq * 256u;
    const int cq = lane >> 4;
    const int rk = (lane & 7) | ((lane & 16) >> 1);
    const int ck = (lane >> 3) & 1;
    const int rv = lane & 15;
    const int cv = lane >> 4;

    float s[16][4];
#pragma unroll
    for (int i = 0; i < 16; ++i)
#pragma unroll
        for (int j = 0; j < 4; ++j) s[i][j] = 0.f;

#pragma unroll
    for (int k = 0; k < 8; ++k) {
        uint32_t qa = qbase + (uint32_t)((((2 * k + cq) ^ (rq & 7))) << 4);
        uint32_t aqh[4], aql[4];
        ldsm4(aqh, QH + qa);
        ldsm4(aql, QL + qa);
#pragma unroll
        for (int nt2 = 0; nt2 < 8; ++nt2) {
            uint32_t ka = (uint32_t)(nt2 * 16 + rk) * 256u
                        + (uint32_t)(((2 * k + ck) ^ (rk & 7)) << 4);
            uint32_t bk[4];
            ldsm4(bk, Kb + ka);
            mma16816h(s[2 * nt2], aqh, bk);
            mma16816h(s[2 * nt2], aql, bk);
            mma16816h(s[2 * nt2 + 1], aqh, bk + 2);
            mma16816h(s[2 * nt2 + 1], aql, bk + 2);
        }
    }

    const int tr0 = T0 + mrow + (lane >> 2);
    const int tr1 = tr0 + 8;
#pragma unroll
    for (int nt = 0; nt < 16; ++nt) {
        int c0 = S0 + nt * 8 + 2 * (lane & 3);
        int c1 = c0 + 1;
        if (c0 > tr0 || c0 < tr0 - 63 || c0 < 0) s[nt][0] = -1e9f;
        if (c1 > tr0 || c1 < tr0 - 63 || c1 < 0) s[nt][1] = -1e9f;
        if (c0 > tr1 || c0 < tr1 - 63 || c0 < 0) s[nt][2] = -1e9f;
        if (c1 > tr1 || c1 < tr1 - 63 || c1 < 0) s[nt][3] = -1e9f;
    }

    float mx0 = -1e30f, mx1 = -1e30f;
#pragma unroll
    for (int nt = 0; nt < 16; ++nt) {
        mx0 = fmaxf(mx0, fmaxf(s[nt][0], s[nt][1]));
        mx1 = fmaxf(mx1, fmaxf(s[nt][2], s[nt][3]));
    }
    mx0 = fmaxf(mx0, __shfl_xor_sync(0xffffffffu, mx0, 1));
    mx0 = fmaxf(mx0, __shfl_xor_sync(0xffffffffu, mx0, 2));
    mx1 = fmaxf(mx1, __shfl_xor_sync(0xffffffffu, mx1, 1));
    mx1 = fmaxf(mx1, __shfl_xor_sync(0xffffffffu, mx1, 2));

    float l0 = 0.f, l1 = 0.f;
#pragma unroll
    for (int nt = 0; nt < 16; ++nt) {
        s[nt][0] = __expf(s[nt][0] - mx0); l0 += s[nt][0];
        s[nt][1] = __expf(s[nt][1] - mx0); l0 += s[nt][1];
        s[nt][2] = __expf(s[nt][2] - mx1); l1 += s[nt][2];
        s[nt][3] = __expf(s[nt][3] - mx1); l1 += s[nt][3];
    }
    l0 += __shfl_xor_sync(0xffffffffu, l0, 1);
    l0 += __shfl_xor_sync(0xffffffffu, l0, 2);
    l1 += __shfl_xor_sync(0xffffffffu, l1, 1);
    l1 += __shfl_xor_sync(0xffffffffu, l1, 2);

    float o[16][4];
#pragma unroll
    for (int i = 0; i < 16; ++i)
#pragma unroll
        for (int j = 0; j < 4; ++j) o[i][j] = 0.f;

#pragma unroll
    for (int ks = 0; ks < 8; ++ks) {
        uint32_t ph[4], pl[4];
        pack_hilo_f16(s[2 * ks][0],     s[2 * ks][1],     ph[0], pl[0]);
        pack_hilo_f16(s[2 * ks][2],     s[2 * ks][3],     ph[1], pl[1]);
        pack_hilo_f16(s[2 * ks + 1][0], s[2 * ks + 1][1], ph[2], pl[2]);
        pack_hilo_f16(s[2 * ks + 1][2], s[2 * ks + 1][3], ph[3], pl[3]);
#pragma unroll
        for (int dt2 = 0; dt2 < 8; ++dt2) {
            uint32_t va = (uint32_t)(16 * ks + rv) * 256u
                        + (uint32_t)(((2 * dt2 + cv) ^ (rv & 7)) << 4);
            uint32_t bv[4];
            ldsm4t(bv, Vb + va);
            mma16816h(o[2 * dt2], ph, bv);
            mma16816h(o[2 * dt2], pl, bv);
            mma16816h(o[2 * dt2 + 1], ph, bv + 2);
            mma16816h(o[2 * dt2 + 1], pl, bv + 2);
        }
    }

    const float inv0 = 1.f / l0, inv1 = 1.f / l1;
    const int r0 = tr0;
    const float gt0 = g_gate[r0 * NH + h];
    const float gt1 = g_gate[(r0 + 8) * NH + h];
    const float ng0 = 1.f - gt0, ng1 = 1.f - gt1;

#pragma unroll
    for (int nt = 0; nt < 16; ++nt) {
        int col = h * DH + nt * 8 + 2 * (lane & 3);
        float2 ga = *(float2*)&g_og[(size_t)r0 * HID + col];
        float2 gb = *(float2*)&g_og[(size_t)(r0 + 8) * HID + col];
        float a0 = ga.x * gt0 + o[nt][0] * inv0 * ng0;
        float a1 = ga.y * gt0 + o[nt][1] * inv0 * ng0;
        float b0 = gb.x * gt1 + o[nt][2] * inv1 * ng1;
        float b1 = gb.y * gt1 + o[nt][3] * inv1 * ng1;
        *(uint32_t*)&g_og16[(size_t)r0 * HID + col] = pack_f16x2(a0, a1);
        *(uint32_t*)&g_og16[(size_t)(r0 + 8) * HID + col] = pack_f16x2(b0, b1);
    }
}

// ---------------- launch --------------------------------------------------------
extern "C" void kernel_launch(void* const* d_in, const int* in_sizes, int n_in,
                              void* d_out, int out_size)
{
    const int*   positions = (const int*)d_in[0];
    const float* hidden    = (const float*)d_in[1];
    const float* k_global  = (const float*)d_in[2];
    const float* v_global  = (const float*)d_in[3];
    const float* w_qkv     = (const float*)d_in[4];
    const float* w_o       = (const float*)d_in[5];
    const float* w_gate    = (const float*)d_in[6];
    const float* b_gate    = (const float*)d_in[7];
    float* out = (float*)d_out;

    float* qkv = nullptr; cudaGetSymbolAddress((void**)&qkv, g_qkv);
    __half *hid16, *wqkv16, *wo16, *og16;
    __half *q_hi, *q_lo, *k16, *v16, *kl16, *vl16;
    cudaGetSymbolAddress((void**)&hid16,   g_hid16);
    cudaGetSymbolAddress((void**)&wqkv16,  g_wqkv16);
    cudaGetSymbolAddress((void**)&wo16,    g_wo16);
    cudaGetSymbolAddress((void**)&og16,    g_og16);
    cudaGetSymbolAddress((void**)&q_hi,    g_q_hi);
    cudaGetSymbolAddress((void**)&q_lo,    g_q_lo);
    cudaGetSymbolAddress((void**)&k16,     g_k16);
    cudaGetSymbolAddress((void**)&v16,     g_v16);
    cudaGetSymbolAddress((void**)&kl16,    g_kl16);
    cudaGetSymbolAddress((void**)&vl16,    g_vl16);

    cudaFuncSetAttribute(gemm_f16, cudaFuncAttributeMaxDynamicSharedMemorySize,
                         GEMM_SMEM);
    cudaFuncSetAttribute(attn_mma, cudaFuncAttributeMaxDynamicSharedMemorySize,
                         ATTN_SMEM);
    cudaFuncSetAttribute(local_mma, cudaFuncAttributeMaxDynamicSharedMemorySize,
                         LOCAL_SMEM);

    build_trig_kernel<<<(T_SEQ * 64 + 255) / 256, 256>>>(positions);

    int n4_hid  = T_SEQ * HID / 4;
    int n4_wqkv = QKV_W * HID / 4;
    int n4_wo   = HID * HID / 4;
    int n4_kv   = T_SEQ * NKV * DH / 4;
    cvt_f16<<<(n4_hid  + 255) / 256, 256>>>(hidden, hid16, n4_hid);
    cvt_f16<<<(n4_wqkv + 255) / 256, 256>>>(w_qkv, wqkv16, n4_wqkv);
    cvt_f16<<<(n4_wo   + 255) / 256, 256>>>(w_o, wo16, n4_wo);
    cvt_f16<<<(n4_kv   + 255) / 256, 256>>>(k_global, k16, n4_kv);
    cvt_f16<<<(n4_kv   + 255) / 256, 256>>>(v_global, v16, n4_kv);

    gemm_f16<<<dim3(QKV_W / 128, T_SEQ / 256), 512, GEMM_SMEM>>>(
        hid16, wqkv16, qkv, T_SEQ, QKV_W, HID);

    rope_gate_kernel<<<T_SEQ, 256>>>(w_gate, b_gate);

    attn_mma<<<dim3(T_SEQ / 32, NKV), 256, ATTN_SMEM>>>(
        q_hi, q_lo, k16, v16);

    local_mma<<<dim3(T_SEQ / 64, NH), 128, LOCAL_SMEM>>>(
        q_hi, q_lo, kl16, vl16);

    gemm_f16<<<dim3(HID / 128, T_SEQ / 256), 512, GEMM_SMEM>>>(
        og16, wo16, out, T_SEQ, HID, HID);
}

// round 17
// speedup vs baseline: 2.6418x; 1.1677x over previous
#include <cuda_runtime.h>
#include <cuda_bf16.h>
#include <cuda_fp16.h>
#include <math.h>
#include <stdint.h>

#define T_SEQ 2048
#define HID   4096
#define NH    32
#define NKV   8
#define GQ    4
#define DH    128
#define WIN   64
#define QKV_W 6144
#define SCALE 0.08838834764831845f

// ---------------- scratch ---------------------------------------------------
__device__ float g_qkv[(size_t)T_SEQ * QKV_W];
__device__ float g_og[(size_t)T_SEQ * HID];     // global attn out (fp32)
__device__ float g_gate[T_SEQ * NH];
__device__ float g_cosT[T_SEQ * 64];
__device__ float g_sinT[T_SEQ * 64];

// fp16 GEMM operands (symmetric single-fp16)
__device__ __half g_hid16[(size_t)T_SEQ * HID];
__device__ __half g_wqkv16[(size_t)QKV_W * HID];
__device__ __half g_wo16[(size_t)HID * HID];
__device__ __half g_og16[(size_t)T_SEQ * HID];   // gated combined out

// attention operands: Q/K/V single fp16 (Q pre-scaled)
__device__ __half g_q16[(size_t)T_SEQ * NH * DH];
__device__ __half g_k16[(size_t)T_SEQ * NKV * DH];
__device__ __half g_v16[(size_t)T_SEQ * NKV * DH];
// local-window k/v (post-rope, from qkv projection), single fp16
__device__ __half g_kl16[(size_t)T_SEQ * NKV * DH];
__device__ __half g_vl16[(size_t)T_SEQ * NKV * DH];

// ================= low-level helpers =========================================
__device__ __forceinline__ uint32_t smem_u32(const void* p) {
    uint32_t a;
    asm("{ .reg .u64 t; cvta.to.shared.u64 t, %1; cvt.u32.u64 %0, t; }"
        : "=r"(a) : "l"(p));
    return a;
}
__device__ __forceinline__ void cpa16(uint32_t dst, const void* src) {
    asm volatile("cp.async.cg.shared.global [%0], [%1], 16;"
                 :: "r"(dst), "l"(src) : "memory");
}
#define CP_COMMIT() asm volatile("cp.async.commit_group;" ::: "memory")
#define CP_WAIT(n)  asm volatile("cp.async.wait_group %0;" :: "n"(n) : "memory")

__device__ __forceinline__ void ldsm4(uint32_t* r, uint32_t addr) {
    asm volatile("ldmatrix.sync.aligned.m8n8.x4.shared.b16 {%0,%1,%2,%3}, [%4];"
                 : "=r"(r[0]), "=r"(r[1]), "=r"(r[2]), "=r"(r[3]) : "r"(addr));
}
__device__ __forceinline__ void ldsm4t(uint32_t* r, uint32_t addr) {
    asm volatile("ldmatrix.sync.aligned.m8n8.x4.trans.shared.b16 {%0,%1,%2,%3}, [%4];"
                 : "=r"(r[0]), "=r"(r[1]), "=r"(r[2]), "=r"(r[3]) : "r"(addr));
}
__device__ __forceinline__ void mma16816h(float* d, const uint32_t* a,
                                          const uint32_t* b) {
    asm volatile(
        "mma.sync.aligned.m16n8k16.row.col.f32.f16.f16.f32 "
        "{%0,%1,%2,%3}, {%4,%5,%6,%7}, {%8,%9}, {%0,%1,%2,%3};"
        : "+f"(d[0]), "+f"(d[1]), "+f"(d[2]), "+f"(d[3])
        : "r"(a[0]), "r"(a[1]), "r"(a[2]), "r"(a[3]), "r"(b[0]), "r"(b[1]));
}
__device__ __forceinline__ uint32_t pack_f16x2(float x, float y) {
    __half2 h = __floats2half2_rn(x, y);
    return *(uint32_t*)&h;
}
__device__ __forceinline__ void pack_hilo_f16(float x, float y,
                                              uint32_t& hi, uint32_t& lo) {
    __half hx = __float2half_rn(x), hy = __float2half_rn(y);
    float rx = x - __half2float(hx), ry = y - __half2float(hy);
    __half lx = __float2half_rn(rx), ly = __float2half_rn(ry);
    hi = (uint32_t)__half_as_ushort(hx) | ((uint32_t)__half_as_ushort(hy) << 16);
    lo = (uint32_t)__half_as_ushort(lx) | ((uint32_t)__half_as_ushort(ly) << 16);
}

// ---------------- trig table -------------------------------------------------
__global__ void build_trig_kernel(const int* __restrict__ positions) {
    int i = blockIdx.x * blockDim.x + threadIdx.x;
    if (i >= T_SEQ * 64) return;
    int t = i >> 6, d = i & 63;
    double inv = pow(10000.0, -(double)d / 64.0);
    double ang = (double)positions[t] * inv;
    g_cosT[i] = (float)cos(ang);
    g_sinT[i] = (float)sin(ang);
}

// ---------------- fp32 -> fp16 single ------------------------------------------
__global__ void __launch_bounds__(256) cvt_f16(
    const float* __restrict__ x, __half* __restrict__ y, int n4)
{
    int i = blockIdx.x * blockDim.x + threadIdx.x;
    if (i >= n4) return;
    float4 v = ((const float4*)x)[i];
    uint2 o;
    o.x = pack_f16x2(v.x, v.y);
    o.y = pack_f16x2(v.z, v.w);
    ((uint2*)y)[i] = o;
}

// ====== symmetric fp16 MMA GEMM (R14 proven: 128x128, 2 CTAs/SM) ==============
#define STAGES 2
#define STG_B  16384
#define GEMM_SMEM (STAGES * STG_B)

__device__ __forceinline__ void load_stage(
    uint32_t sbase, int stage, int c,
    const __half* __restrict__ A, const __half* __restrict__ B,
    int bm, int bn, int K, int tid)
{
    const int k0 = c * 32;
    const uint32_t st = sbase + stage * STG_B;
#pragma unroll
    for (int j = 0; j < 4; ++j) {
        int l = tid + j * 256;
        int t = j >> 1;
        int li = l & 511;
        int row = li >> 2;
        int ch = li & 3;
        uint32_t dst = st + (uint32_t)t * 8192u + (uint32_t)row * 64u
                     + (uint32_t)((ch ^ ((row >> 1) & 3)) << 4);
        const __half* src = (t == 0)
            ? A + (size_t)(bm + row) * K + k0 + ch * 8
            : B + (size_t)(bn + row) * K + k0 + ch * 8;
        cpa16(dst, src);
    }
}

__global__ void __launch_bounds__(256, 2) gemm_f16(
    const __half* __restrict__ A, const __half* __restrict__ B,
    float* __restrict__ C, int M, int N, int K)
{
    extern __shared__ char smem[];
    const uint32_t sbase = smem_u32(smem);
    const int tid = threadIdx.x;
    const int wid = tid >> 5, lane = tid & 31;
    const int bm = blockIdx.y * 128, bn = blockIdx.x * 128;
    const int wm = (wid & 3) * 32;
    const int wn = (wid >> 2) * 64;

    float acc[2][8][4];
#pragma unroll
    for (int mi = 0; mi < 2; ++mi)
#pragma unroll
        for (int ni = 0; ni < 8; ++ni)
#pragma unroll
            for (int k = 0; k < 4; ++k) acc[mi][ni][k] = 0.f;

    const int nch = K / 32;

    load_stage(sbase, 0, 0, A, B, bm, bn, K, tid);
    CP_COMMIT();

    uint32_t offA[2], offB[4];
#pragma unroll
    for (int mi = 0; mi < 2; ++mi) {
        int row = wm + mi * 16 + (lane & 15);
        offA[mi] = (uint32_t)row * 64u;
    }
#pragma unroll
    for (int nj = 0; nj < 4; ++nj) {
        int row = wn + nj * 16 + ((lane >> 4) << 3) + (lane & 7);
        offB[nj] = (uint32_t)row * 64u;
    }
    const int chA = (lane >> 4);
    const int chB = ((lane >> 3) & 1);
    int swA[2], swB[4];
#pragma unroll
    for (int mi = 0; mi < 2; ++mi) {
        int row = wm + mi * 16 + (lane & 15);
        swA[mi] = (row >> 1) & 3;
    }
#pragma unroll
    for (int nj = 0; nj < 4; ++nj) {
        int row = wn + nj * 16 + ((lane >> 4) << 3) + (lane & 7);
        swB[nj] = (row >> 1) & 3;
    }

    for (int c = 0; c < nch; ++c) {
        CP_WAIT(0);
        __syncthreads();
        if (c + 1 < nch)
            load_stage(sbase, (c + 1) & 1, c + 1, A, B, bm, bn, K, tid);
        CP_COMMIT();

        const uint32_t st = sbase + (uint32_t)(c & 1) * STG_B;
#pragma unroll
        for (int ks = 0; ks < 2; ++ks) {
            uint32_t ra[2][4], rb[4][4];
#pragma unroll
            for (int mi = 0; mi < 2; ++mi) {
                int ch = ks * 2 + chA;
                uint32_t o = offA[mi] + (uint32_t)((ch ^ swA[mi]) << 4);
                ldsm4(ra[mi], st + o);
            }
#pragma unroll
            for (int nj = 0; nj < 4; ++nj) {
                int ch = ks * 2 + chB;
                uint32_t o = offB[nj] + (uint32_t)((ch ^ swB[nj]) << 4);
                ldsm4(rb[nj], st + 8192u + o);
            }
#pragma unroll
            for (int mi = 0; mi < 2; ++mi)
#pragma unroll
                for (int ni = 0; ni < 8; ++ni) {
                    const uint32_t* b2 = &rb[ni >> 1][(ni & 1) * 2];
                    mma16816h(acc[mi][ni], ra[mi], b2);
                }
        }
        __syncthreads();
    }

    const int g = lane >> 2, q = lane & 3;
#pragma unroll
    for (int mi = 0; mi < 2; ++mi)
#pragma unroll
        for (int ni = 0; ni < 8; ++ni) {
            int r0 = bm + wm + mi * 16 + g;
            int col = bn + wn + ni * 8 + q * 2;
            float2 v0 = make_float2(acc[mi][ni][0], acc[mi][ni][1]);
            float2 v1 = make_float2(acc[mi][ni][2], acc[mi][ni][3]);
            *(float2*)(C + (size_t)r0 * N + col) = v0;
            *(float2*)(C + (size_t)(r0 + 8) * N + col) = v1;
        }
}

// ---------------- RoPE + gate + fp16 exports ------------------------------------
__global__ void __launch_bounds__(256) rope_gate_kernel(
    const float* __restrict__ w_gate, const float* __restrict__ b_gate)
{
    int t = blockIdx.x;
    float* row = g_qkv + (size_t)t * QKV_W;

    for (int idx = threadIdx.x; idx < 48 * 64; idx += 256) {
        int head = idx >> 6;
        int d = idx & 63;
        if (head < NH) {                       // q heads: rope + scaled fp16
            int base = head * DH;
            float c = g_cosT[t * 64 + d];
            float s = g_sinT[t * 64 + d];
            float x1 = row[base + d];
            float x2 = row[base + d + 64];
            float y1 = x1 * c - x2 * s;
            float y2 = x2 * c + x1 * s;
            row[base + d]      = y1;           // for gate
            row[base + d + 64] = y2;
            size_t qi = ((size_t)t * NH + head) * DH + d;
            g_q16[qi]      = __float2half_rn(y1 * SCALE);
            g_q16[qi + 64] = __float2half_rn(y2 * SCALE);
        } else if (head < NH + NKV) {          // k heads: rope + single fp16
            int gk = head - NH;
            int base = HID + gk * DH;
            float c = g_cosT[t * 64 + d];
            float s = g_sinT[t * 64 + d];
            float x1 = row[base + d];
            float x2 = row[base + d + 64];
            float y1 = x1 * c - x2 * s;
            float y2 = x2 * c + x1 * s;
            size_t ki = ((size_t)t * NKV + gk) * DH + d;
            g_kl16[ki]      = __float2half_rn(y1);
            g_kl16[ki + 64] = __float2half_rn(y2);
        } else {                               // v heads: single fp16
            int gv = head - NH - NKV;
            int base = HID + NKV * DH + gv * DH;
            size_t vi = ((size_t)t * NKV + gv) * DH + d;
            g_vl16[vi]      = __float2half_rn(row[base + d]);
            g_vl16[vi + 64] = __float2half_rn(row[base + d + 64]);
        }
    }
    __syncthreads();

    int wid = threadIdx.x >> 5, lane = threadIdx.x & 31;
    for (int h = wid; h < NH; h += 8) {
        const float* q = row + h * DH;
        const float* w = w_gate + h * DH;
        float acc = q[lane] * w[lane] + q[lane + 32] * w[lane + 32]
                  + q[lane + 64] * w[lane + 64] + q[lane + 96] * w[lane + 96];
#pragma unroll
        for (int off = 16; off; off >>= 1)
            acc += __shfl_xor_sync(0xffffffffu, acc, off);
        if (lane == 0)
            g_gate[t * NH + h] = 1.f / (1.f + __expf(-(acc + b_gate[h])));
    }
}

// ================= MMA flash attention (global causal, GQA-shared KV) =========
// Q single fp16 (1 QK MMA per k16), P hi/lo (2 PV MMAs per k16).
#define ATTN_SMEM 98304   // Q 32KB + 2 x (K 16KB + V 16KB)

__device__ __forceinline__ void attn_load_kv(
    uint32_t buf, int s0, int g, int tid,
    const __half* k16, const __half* v16)
{
#pragma unroll
    for (int j = 0; j < 4; ++j) {
        int slot = tid + j * 256;
        int row = slot >> 4;
        int ch = slot & 15;
        uint32_t off = (uint32_t)row * 256u + (uint32_t)((ch ^ (row & 7)) << 4);
        size_t gi = ((size_t)(s0 + row) * NKV + g) * DH + ch * 8;
        cpa16(buf + off, k16 + gi);
        cpa16(buf + 16384u + off, v16 + gi);
    }
}

__global__ void __launch_bounds__(256, 1) attn_mma(
    const __half* __restrict__ q_g,
    const __half* __restrict__ k_g, const __half* __restrict__ v_g)
{
    extern __shared__ char smem[];
    const uint32_t sb = smem_u32(smem);
    const int tid = threadIdx.x, wid = tid >> 5, lane = tid & 31;
    const int g = blockIdx.y;
    const int T0 = (gridDim.x - 1 - blockIdx.x) * 32;   // heavy blocks first
    const int nblk = (T0 + 32 + 63) / 64;

    const uint32_t QB = sb;
    const uint32_t KV0 = sb + 32768u;

#pragma unroll
    for (int j = 0; j < 8; ++j) {
        int slot = tid + j * 256;
        int row = slot >> 4;               // 0..127
        int ch = slot & 15;
        uint32_t off = (uint32_t)row * 256u + (uint32_t)((ch ^ (row & 7)) << 4);
        int tt = row & 31;
        int hi = row >> 5;
        size_t gi = ((size_t)(T0 + tt) * NH + (g * GQ + hi)) * DH + ch * 8;
        cpa16(QB + off, q_g + gi);
    }
    attn_load_kv(KV0, 0, g, tid, k_g, v_g);
    CP_COMMIT();

    const int mrow = wid * 16;
    const int rq = mrow + (lane & 15);
    const uint32_t qbase = (uint32_t)rq * 256u;
    const int cq = lane >> 4;
    const int rk = (lane & 7) | ((lane & 16) >> 1);
    const int ck = (lane >> 3) & 1;
    const int rv = lane & 15;
    const int cv = lane >> 4;
    const int wh = mrow >> 5;
    const int wtt = mrow & 31;

    float o[16][4];
#pragma unroll
    for (int i = 0; i < 16; ++i)
#pragma unroll
        for (int j = 0; j < 4; ++j) o[i][j] = 0.f;
    float m0 = -1e30f, m1 = -1e30f, l0 = 0.f, l1 = 0.f;

    for (int blk = 0; blk < nblk; ++blk) {
        if (blk + 1 < nblk)
            attn_load_kv(KV0 + (uint32_t)((blk + 1) & 1) * 32768u,
                         (blk + 1) * 64, g, tid, k_g, v_g);
        CP_COMMIT();
        CP_WAIT(1);
        __syncthreads();

        const int s0 = blk * 64;
        const bool active = (s0 <= T0 + wtt + 15);
        if (active) {
            const uint32_t buf = KV0 + (uint32_t)(blk & 1) * 32768u;
            const uint32_t Kb = buf, Vb = buf + 16384u;

            float s[8][4];
#pragma unroll
            for (int i = 0; i < 8; ++i)
#pragma unroll
                for (int j = 0; j < 4; ++j) s[i][j] = 0.f;

#pragma unroll
            for (int k = 0; k < 8; ++k) {
                uint32_t qa = qbase + (uint32_t)((((2 * k + cq) ^ (rq & 7))) << 4);
                uint32_t aq[4];
                ldsm4(aq, QB + qa);
#pragma unroll
                for (int nt2 = 0; nt2 < 4; ++nt2) {
                    uint32_t ka = (uint32_t)(nt2 * 16 + rk) * 256u
                                + (uint32_t)(((2 * k + ck) ^ (rk & 7)) << 4);
                    uint32_t bk[4];
                    ldsm4(bk, Kb + ka);
                    mma16816h(s[2 * nt2], aq, bk);
                    mma16816h(s[2 * nt2 + 1], aq, bk + 2);
                }
            }

            if (s0 + 63 > T0 + wtt) {
                const int tr0 = T0 + wtt + (lane >> 2);
                const int tr1 = tr0 + 8;
#pragma unroll
                for (int nt = 0; nt < 8; ++nt) {
                    int sc = s0 + nt * 8 + 2 * (lane & 3);
                    if (sc > tr0)     s[nt][0] = -1e9f;
                    if (sc + 1 > tr0) s[nt][1] = -1e9f;
                    if (sc > tr1)     s[nt][2] = -1e9f;
                    if (sc + 1 > tr1) s[nt][3] = -1e9f;
                }
            }

            float mx0 = -1e30f, mx1 = -1e30f;
#pragma unroll
            for (int nt = 0; nt < 8; ++nt) {
                mx0 = fmaxf(mx0, fmaxf(s[nt][0], s[nt][1]));
                mx1 = fmaxf(mx1, fmaxf(s[nt][2], s[nt][3]));
            }
            mx0 = fmaxf(mx0, __shfl_xor_sync(0xffffffffu, mx0, 1));
            mx0 = fmaxf(mx0, __shfl_xor_sync(0xffffffffu, mx0, 2));
            mx1 = fmaxf(mx1, __shfl_xor_sync(0xffffffffu, mx1, 1));
            mx1 = fmaxf(mx1, __shfl_xor_sync(0xffffffffu, mx1, 2));
            float nm0 = fmaxf(m0, mx0), nm1 = fmaxf(m1, mx1);
            float cor0 = __expf(m0 - nm0), cor1 = __expf(m1 - nm1);
            m0 = nm0; m1 = nm1;

            float sum0 = 0.f, sum1 = 0.f;
#pragma unroll
            for (int nt = 0; nt < 8; ++nt) {
                s[nt][0] = __expf(s[nt][0] - m0); sum0 += s[nt][0];
                s[nt][1] = __expf(s[nt][1] - m0); sum0 += s[nt][1];
                s[nt][2] = __expf(s[nt][2] - m1); sum1 += s[nt][2];
                s[nt][3] = __expf(s[nt][3] - m1); sum1 += s[nt][3];
            }
            l0 = l0 * cor0 + sum0;
            l1 = l1 * cor1 + sum1;
#pragma unroll
            for (int i = 0; i < 16; ++i) {
                o[i][0] *= cor0; o[i][1] *= cor0;
                o[i][2] *= cor1; o[i][3] *= cor1;
            }

            uint32_t ph[4][4], pl[4][4];
#pragma unroll
            for (int ks = 0; ks < 4; ++ks) {
                pack_hilo_f16(s[2 * ks][0],     s[2 * ks][1],     ph[ks][0], pl[ks][0]);
                pack_hilo_f16(s[2 * ks][2],     s[2 * ks][3],     ph[ks][1], pl[ks][1]);
                pack_hilo_f16(s[2 * ks + 1][0], s[2 * ks + 1][1], ph[ks][2], pl[ks][2]);
                pack_hilo_f16(s[2 * ks + 1][2], s[2 * ks + 1][3], ph[ks][3], pl[ks][3]);
            }

#pragma unroll
            for (int ks = 0; ks < 4; ++ks) {
#pragma unroll
                for (int dt2 = 0; dt2 < 8; ++dt2) {
                    uint32_t va = (uint32_t)(16 * ks + rv) * 256u
                                + (uint32_t)(((2 * dt2 + cv) ^ (rv & 7)) << 4);
                    uint32_t bv[4];
                    ldsm4t(bv, Vb + va);
                    mma16816h(o[2 * dt2], ph[ks], bv);
                    mma16816h(o[2 * dt2], pl[ks], bv);
                    mma16816h(o[2 * dt2 + 1], ph[ks], bv + 2);
                    mma16816h(o[2 * dt2 + 1], pl[ks], bv + 2);
                }
            }
        }
        __syncthreads();
    }

    l0 += __shfl_xor_sync(0xffffffffu, l0, 1);
    l0 += __shfl_xor_sync(0xffffffffu, l0, 2);
    l1 += __shfl_xor_sync(0xffffffffu, l1, 1);
    l1 += __shfl_xor_sync(0xffffffffu, l1, 2);
    float inv0 = 1.f / l0, inv1 = 1.f / l1;

    const int h = g * GQ + wh;
    const int t0r = T0 + wtt + (lane >> 2);
#pragma unroll
    for (int nt = 0; nt < 16; ++nt) {
        int col = h * DH + nt * 8 + 2 * (lane & 3);
        float2 a = make_float2(o[nt][0] * inv0, o[nt][1] * inv0);
        float2 b = make_float2(o[nt][2] * inv1, o[nt][3] * inv1);
        *(float2*)&g_og[(size_t)t0r * HID + col] = a;
        *(float2*)&g_og[(size_t)(t0r + 8) * HID + col] = b;
    }
}

// ================= MMA local band attention + gate combine ====================
#define LOCAL_SMEM 81920   // Q 16KB + K 32KB + V 32KB

__global__ void __launch_bounds__(128, 1) local_mma(
    const __half* __restrict__ q_g,
    const __half* __restrict__ k_g, const __half* __restrict__ v_g)
{
    extern __shared__ char smem[];
    const uint32_t sb = smem_u32(smem);
    const int tid = threadIdx.x, wid = tid >> 5, lane = tid & 31;
    const int h = blockIdx.y, g = h >> 2;
    const int T0 = blockIdx.x * 64;
    const int S0 = T0 - 64;

    const uint32_t QB = sb;
    const uint32_t Kb = sb + 16384u, Vb = sb + 49152u;

#pragma unroll
    for (int j = 0; j < 8; ++j) {
        int slot = tid + j * 128;          // 0..1023
        int row = slot >> 4;
        int ch = slot & 15;
        uint32_t off = (uint32_t)row * 256u + (uint32_t)((ch ^ (row & 7)) << 4);
        size_t gi = ((size_t)(T0 + row) * NH + h) * DH + ch * 8;
        cpa16(QB + off, q_g + gi);
    }
#pragma unroll
    for (int j = 0; j < 16; ++j) {
        int slot = tid + j * 128;
        int row = slot >> 4;
        int ch = slot & 15;
        uint32_t off = (uint32_t)row * 256u + (uint32_t)((ch ^ (row & 7)) << 4);
        int srow = S0 + row;
        if (srow < 0) srow = 0;
        size_t gi = ((size_t)srow * NKV + g) * DH + ch * 8;
        cpa16(Kb + off, k_g + gi);
        cpa16(Vb + off, v_g + gi);
    }
    CP_COMMIT();
    CP_WAIT(0);
    __syncthreads();

    const int mrow = wid * 16;
    const int rq = mrow + (lane & 15);
    const uint32_t qbase = (uint32_t)rq * 256u;
    const int cq = lane >> 4;
    const int rk = (lane & 7) | ((lane & 16) >> 1);
    const int ck = (lane >> 3) & 1;
    const int rv = lane & 15;
    const int cv = lane >> 4;

    float s[16][4];
#pragma unroll
    for (int i = 0; i < 16; ++i)
#pragma unroll
        for (int j = 0; j < 4; ++j) s[i][j] = 0.f;

#pragma unroll
    for (int k = 0; k < 8; ++k) {
        uint32_t qa = qbase + (uint32_t)((((2 * k + cq) ^ (rq & 7))) << 4);
        uint32_t aq[4];
        ldsm4(aq, QB + qa);
#pragma unroll
        for (int nt2 = 0; nt2 < 8; ++nt2) {
            uint32_t ka = (uint32_t)(nt2 * 16 + rk) * 256u
                        + (uint32_t)(((2 * k + ck) ^ (rk & 7)) << 4);
            uint32_t bk[4];
            ldsm4(bk, Kb + ka);
            mma16816h(s[2 * nt2], aq, bk);
            mma16816h(s[2 * nt2 + 1], aq, bk + 2);
        }
    }

    const int tr0 = T0 + mrow + (lane >> 2);
    const int tr1 = tr0 + 8;
#pragma unroll
    for (int nt = 0; nt < 16; ++nt) {
        int c0 = S0 + nt * 8 + 2 * (lane & 3);
        int c1 = c0 + 1;
        if (c0 > tr0 || c0 < tr0 - 63 || c0 < 0) s[nt][0] = -1e9f;
        if (c1 > tr0 || c1 < tr0 - 63 || c1 < 0) s[nt][1] = -1e9f;
        if (c0 > tr1 || c0 < tr1 - 63 || c0 < 0) s[nt][2] = -1e9f;
        if (c1 > tr1 || c1 < tr1 - 63 || c1 < 0) s[nt][3] = -1e9f;
    }

    float mx0 = -1e30f, mx1 = -1e30f;
#pragma unroll
    for (int nt = 0; nt < 16; ++nt) {
        mx0 = fmaxf(mx0, fmaxf(s[nt][0], s[nt][1]));
        mx1 = fmaxf(mx1, fmaxf(s[nt][2], s[nt][3]));
    }
    mx0 = fmaxf(mx0, __shfl_xor_sync(0xffffffffu, mx0, 1));
    mx0 = fmaxf(mx0, __shfl_xor_sync(0xffffffffu, mx0, 2));
    mx1 = fmaxf(mx1, __shfl_xor_sync(0xffffffffu, mx1, 1));
    mx1 = fmaxf(mx1, __shfl_xor_sync(0xffffffffu, mx1, 2));

    float l0 = 0.f, l1 = 0.f;
#pragma unroll
    for (int nt = 0; nt < 16; ++nt) {
        s[nt][0] = __expf(s[nt][0] - mx0); l0 += s[nt][0];
        s[nt][1] = __expf(s[nt][1] - mx0); l0 += s[nt][1];
        s[nt][2] = __expf(s[nt][2] - mx1); l1 += s[nt][2];
        s[nt][3] = __expf(s[nt][3] - mx1); l1 += s[nt][3];
    }
    l0 += __shfl_xor_sync(0xffffffffu, l0, 1);
    l0 += __shfl_xor_sync(0xffffffffu, l0, 2);
    l1 += __shfl_xor_sync(0xffffffffu, l1, 1);
    l1 += __shfl_xor_sync(0xffffffffu, l1, 2);

    float o[16][4];
#pragma unroll
    for (int i = 0; i < 16; ++i)
#pragma unroll
        for (int j = 0; j < 4; ++j) o[i][j] = 0.f;

#pragma unroll
    for (int ks = 0; ks < 8; ++ks) {
        uint32_t ph[4], pl[4];
        pack_hilo_f16(s[2 * ks][0],     s[2 * ks][1],     ph[0], pl[0]);
        pack_hilo_f16(s[2 * ks][2],     s[2 * ks][3],     ph[1], pl[1]);
        pack_hilo_f16(s[2 * ks + 1][0], s[2 * ks + 1][1], ph[2], pl[2]);
        pack_hilo_f16(s[2 * ks + 1][2], s[2 * ks + 1][3], ph[3], pl[3]);
#pragma unroll
        for (int dt2 = 0; dt2 < 8; ++dt2) {
            uint32_t va = (uint32_t)(16 * ks + rv) * 256u
                        + (uint32_t)(((2 * dt2 + cv) ^ (rv & 7)) << 4);
            uint32_t bv[4];
            ldsm4t(bv, Vb + va);
            mma16816h(o[2 * dt2], ph, bv);
            mma16816h(o[2 * dt2], pl, bv);
            mma16816h(o[2 * dt2 + 1], ph, bv + 2);
            mma16816h(o[2 * dt2 + 1], pl, bv + 2);
        }
    }

    const float inv0 = 1.f / l0, inv1 = 1.f / l1;
    const int r0 = tr0;
    const float gt0 = g_gate[r0 * NH + h];
    const float gt1 = g_gate[(r0 + 8) * NH + h];
    const float ng0 = 1.f - gt0, ng1 = 1.f - gt1;

#pragma unroll
    for (int nt = 0; nt < 16; ++nt) {
        int col = h * DH + nt * 8 + 2 * (lane & 3);
        float2 ga = *(float2*)&g_og[(size_t)r0 * HID + col];
        float2 gb = *(float2*)&g_og[(size_t)(r0 + 8) * HID + col];
        float a0 = ga.x * gt0 + o[nt][0] * inv0 * ng0;
        float a1 = ga.y * gt0 + o[nt][1] * inv0 * ng0;
        float b0 = gb.x * gt1 + o[nt][2] * inv1 * ng1;
        float b1 = gb.y * gt1 + o[nt][3] * inv1 * ng1;
        *(uint32_t*)&g_og16[(size_t)r0 * HID + col] = pack_f16x2(a0, a1);
        *(uint32_t*)&g_og16[(size_t)(r0 + 8) * HID + col] = pack_f16x2(b0, b1);
    }
}

// ---------------- launch --------------------------------------------------------
extern "C" void kernel_launch(void* const* d_in, const int* in_sizes, int n_in,
                              void* d_out, int out_size)
{
    const int*   positions = (const int*)d_in[0];
    const float* hidden    = (const float*)d_in[1];
    const float* k_global  = (const float*)d_in[2];
    const float* v_global  = (const float*)d_in[3];
    const float* w_qkv     = (const float*)d_in[4];
    const float* w_o       = (const float*)d_in[5];
    const float* w_gate    = (const float*)d_in[6];
    const float* b_gate    = (const float*)d_in[7];
    float* out = (float*)d_out;

    float* qkv = nullptr; cudaGetSymbolAddress((void**)&qkv, g_qkv);
    __half *hid16, *wqkv16, *wo16, *og16;
    __half *q16, *k16, *v16, *kl16, *vl16;
    cudaGetSymbolAddress((void**)&hid16,   g_hid16);
    cudaGetSymbolAddress((void**)&wqkv16,  g_wqkv16);
    cudaGetSymbolAddress((void**)&wo16,    g_wo16);
    cudaGetSymbolAddress((void**)&og16,    g_og16);
    cudaGetSymbolAddress((void**)&q16,     g_q16);
    cudaGetSymbolAddress((void**)&k16,     g_k16);
    cudaGetSymbolAddress((void**)&v16,     g_v16);
    cudaGetSymbolAddress((void**)&kl16,    g_kl16);
    cudaGetSymbolAddress((void**)&vl16,    g_vl16);

    cudaFuncSetAttribute(gemm_f16, cudaFuncAttributeMaxDynamicSharedMemorySize,
                         GEMM_SMEM);
    cudaFuncSetAttribute(attn_mma, cudaFuncAttributeMaxDynamicSharedMemorySize,
                         ATTN_SMEM);
    cudaFuncSetAttribute(local_mma, cudaFuncAttributeMaxDynamicSharedMemorySize,
                         LOCAL_SMEM);

    build_trig_kernel<<<(T_SEQ * 64 + 255) / 256, 256>>>(positions);

    int n4_hid  = T_SEQ * HID / 4;
    int n4_wqkv = QKV_W * HID / 4;
    int n4_wo   = HID * HID / 4;
    int n4_kv   = T_SEQ * NKV * DH / 4;
    cvt_f16<<<(n4_hid  + 255) / 256, 256>>>(hidden, hid16, n4_hid);
    cvt_f16<<<(n4_wqkv + 255) / 256, 256>>>(w_qkv, wqkv16, n4_wqkv);
    cvt_f16<<<(n4_wo   + 255) / 256, 256>>>(w_o, wo16, n4_wo);
    cvt_f16<<<(n4_kv   + 255) / 256, 256>>>(k_global, k16, n4_kv);
    cvt_f16<<<(n4_kv   + 255) / 256, 256>>>(v_global, v16, n4_kv);

    gemm_f16<<<dim3(QKV_W / 128, T_SEQ / 128), 256, GEMM_SMEM>>>(
        hid16, wqkv16, qkv, T_SEQ, QKV_W, HID);

    rope_gate_kernel<<<T_SEQ, 256>>>(w_gate, b_gate);

    attn_mma<<<dim3(T_SEQ / 32, NKV), 256, ATTN_SMEM>>>(
        q16, k16, v16);

    local_mma<<<dim3(T_SEQ / 64, NH), 128, LOCAL_SMEM>>>(
        q16, kl16, vl16);

    gemm_f16<<<dim3(HID / 128, T_SEQ / 128), 256, GEMM_SMEM>>>(
        og16, wo16, out, T_SEQ, HID, HID);
}